// round 2
// baseline (speedup 1.0000x reference)
#include <cuda_runtime.h>
#include <cstdint>

#define NN   20000
#define EE   320000
#define DD   256
#define OUTD 256

// ---------------- scratch (static device globals; no allocs allowed) ----------------
__device__ __align__(16) float g_h  [(size_t)NN * DD];
__device__ __align__(16) float g_hw [(size_t)NN * DD];
__device__ __align__(16) float g_acc[(size_t)NN * DD];
__device__ float g_esrc[NN];
__device__ float g_edst[NN];
__device__ float g_sum [NN];
__device__ int   g_maxord[NN];
__device__ float g_e  [EE];
__device__ int   g_src[EE];
__device__ int   g_dst[EE];
__device__ __align__(16) float g_wfold[DD * OUTD];
__device__ int   g_is64;

// ---------------- helpers ----------------
__device__ __forceinline__ int f2o(float f) {
    int b = __float_as_int(f);
    return b >= 0 ? b : (b ^ 0x7FFFFFFF);
}
__device__ __forceinline__ float o2f(int o) {
    return __int_as_float(o >= 0 ? o : (o ^ 0x7FFFFFFF));
}

// ---------------- dtype detection + index conversion ----------------
__global__ void k_detect(const int* ei32) {
    if (threadIdx.x == 0 && blockIdx.x == 0) {
        int all0 = 1;
        for (int i = 0; i < 128; i++)
            if (ei32[2 * i + 1] != 0) { all0 = 0; break; }
        g_is64 = all0;  // int64 little-endian => every high word of src[0..127] is 0
    }
}

__global__ void k_convert(const void* ei) {
    int i = blockIdx.x * blockDim.x + threadIdx.x;
    int is64 = g_is64;
    for (; i < EE; i += gridDim.x * blockDim.x) {
        int s, t;
        if (is64) {
            const long long* p = (const long long*)ei;
            s = (int)p[i]; t = (int)p[EE + i];
        } else {
            const int* p = (const int*)ei;
            s = p[i]; t = p[EE + i];
        }
        g_src[i] = s; g_dst[i] = t;
    }
}

// ---------------- SGEMM: C[M,Nc] = (reluA? relu(A) : A)[M,K] @ B[K,Nc] ----------------
// BM=BN=128, BK=8, 256 threads, 8x8 microtile. Nc must be a multiple of 128 (always 256 here).
#define BM 128
#define BN 128
#define BK 8

template <bool RELU_A>
__global__ void __launch_bounds__(256, 2)
k_sgemm(int M, int K, int Nc,
        const float* __restrict__ A, const float* __restrict__ B, float* __restrict__ C) {
    __shared__ float As[BK][BM];
    __shared__ float Bs[BK][BN];
    const int tid  = threadIdx.x;
    const int rowBase = blockIdx.y * BM;
    const int colBase = blockIdx.x * BN;

    const int aRow = tid >> 1;          // 0..127
    const int aCol = (tid & 1) * 4;     // 0 or 4
    const int bRow = tid >> 5;          // 0..7
    const int bCol = (tid & 31) * 4;    // 0..124

    const int tRow = (tid >> 4) * 8;
    const int tCol = (tid & 15) * 8;

    float acc[8][8] = {};
    float rM[8], rN[8];

    const float* Ap = A + (size_t)rowBase * K;
    const float* Bp = B + colBase;

    for (int kk = 0; kk < K; kk += BK) {
        // load A tile (guard M edge), transpose into As[k][row]
        {
            float4 v = make_float4(0.f, 0.f, 0.f, 0.f);
            if (rowBase + aRow < M)
                v = *(const float4*)(Ap + (size_t)aRow * K + kk + aCol);
            if (RELU_A) {
                v.x = fmaxf(v.x, 0.f); v.y = fmaxf(v.y, 0.f);
                v.z = fmaxf(v.z, 0.f); v.w = fmaxf(v.w, 0.f);
            }
            As[aCol + 0][aRow] = v.x; As[aCol + 1][aRow] = v.y;
            As[aCol + 2][aRow] = v.z; As[aCol + 3][aRow] = v.w;
        }
        // load B tile (K rows always valid: K==256)
        {
            float4 v = *(const float4*)(Bp + (size_t)(kk + bRow) * Nc + bCol);
            *(float4*)&Bs[bRow][bCol] = v;
        }
        __syncthreads();

        #pragma unroll
        for (int k = 0; k < BK; k++) {
            #pragma unroll
            for (int i = 0; i < 8; i++) rM[i] = As[k][tRow + i];
            #pragma unroll
            for (int j = 0; j < 8; j++) rN[j] = Bs[k][tCol + j];
            #pragma unroll
            for (int i = 0; i < 8; i++)
                #pragma unroll
                for (int j = 0; j < 8; j++)
                    acc[i][j] = fmaf(rM[i], rN[j], acc[i][j]);
        }
        __syncthreads();
    }

    #pragma unroll
    for (int i = 0; i < 8; i++) {
        int gr = rowBase + tRow + i;
        if (gr < M) {
            float* cp = C + (size_t)gr * Nc + colBase + tCol;
            *(float4*)(cp + 0) = make_float4(acc[i][0], acc[i][1], acc[i][2], acc[i][3]);
            *(float4*)(cp + 4) = make_float4(acc[i][4], acc[i][5], acc[i][6], acc[i][7]);
        }
    }
}

// ---------------- per-node attention dots: e_src = hw@asrc, e_dst = hw@adst ----------------
__global__ void k_nodedots(const float* __restrict__ asrc, const float* __restrict__ adst) {
    int g = blockIdx.x * blockDim.x + threadIdx.x;
    int node = g >> 5, lane = g & 31;
    if (node >= NN) return;
    const float4* row = (const float4*)(g_hw + (size_t)node * DD);
    const float4* Ap  = (const float4*)asrc;
    const float4* Bp  = (const float4*)adst;
    float s = 0.f, d = 0.f;
    #pragma unroll
    for (int i = lane; i < DD / 4; i += 32) {
        float4 v = row[i], a = Ap[i], b = Bp[i];
        s += v.x * a.x + v.y * a.y + v.z * a.z + v.w * a.w;
        d += v.x * b.x + v.y * b.y + v.z * b.z + v.w * b.w;
    }
    #pragma unroll
    for (int o = 16; o > 0; o >>= 1) {
        s += __shfl_down_sync(0xFFFFFFFFu, s, o);
        d += __shfl_down_sync(0xFFFFFFFFu, d, o);
    }
    if (lane == 0) { g_esrc[node] = s; g_edst[node] = d; }
}

// ---------------- per-layer reset ----------------
__global__ void k_reset() {
    int i = blockIdx.x * blockDim.x + threadIdx.x;
    if (i < NN * DD) g_acc[i] = 0.f;
    if (i < NN) { g_sum[i] = 0.f; g_maxord[i] = (int)0x80000000; }
}

// ---------------- edge pass 1: e = leaky_relu(es[src]+ed[dst]); segment max ----------------
__global__ void k_edge_e() {
    int i = blockIdx.x * blockDim.x + threadIdx.x;
    if (i >= EE) return;
    int s = g_src[i], t = g_dst[i];
    float v = g_esrc[s] + g_edst[t];
    v = v > 0.f ? v : 0.2f * v;
    g_e[i] = v;
    atomicMax(&g_maxord[t], f2o(v));
}

// ---------------- edge pass 2: ee = exp(e-m); scatter ee*hw[src] into acc[dst]; sum ee ----------------
__global__ void k_scatter() {
    int g = blockIdx.x * blockDim.x + threadIdx.x;
    int eid = g >> 5, lane = g & 31;
    if (eid >= EE) return;
    int s = g_src[eid], t = g_dst[eid];
    float ee = __expf(g_e[eid] - o2f(g_maxord[t]));
    if (lane == 0) atomicAdd(&g_sum[t], ee);
    const float4* hs = (const float4*)(g_hw + (size_t)s * DD);
    float* ad = g_acc + (size_t)t * DD;
    #pragma unroll
    for (int i = lane; i < DD / 4; i += 32) {
        float4 v = hs[i];
        asm volatile("red.global.add.v4.f32 [%0], {%1, %2, %3, %4};"
                     :: "l"(ad + i * 4),
                        "f"(ee * v.x), "f"(ee * v.y), "f"(ee * v.z), "f"(ee * v.w)
                     : "memory");
    }
}

// ---------------- normalize + bias: h = acc/denom + b ----------------
__global__ void k_norm(const float* __restrict__ b) {
    int i = blockIdx.x * blockDim.x + threadIdx.x;
    if (i >= NN * DD) return;
    int n = i >> 8, d = i & 255;   // DD == 256
    float s = g_sum[n];
    float v = (s > 0.f) ? g_acc[i] / s : 0.f;
    g_h[i] = v + b[d];
}

// ---------------- fold W3: relu(concat(h,h))@W3 == relu(h)@(W3_top+W3_bot) ----------------
__global__ void k_fold(const float* __restrict__ W3) {
    int i = blockIdx.x * blockDim.x + threadIdx.x;
    if (i < DD * OUTD) g_wfold[i] = W3[i] + W3[DD * OUTD + i];
}

// ---------------- launch ----------------
extern "C" void kernel_launch(void* const* d_in, const int* in_sizes, int n_in,
                              void* d_out, int out_size) {
    const float* x     = (const float*)d_in[0];
    const void*  ei    = d_in[1];
    const float* W1    = (const float*)d_in[2];
    const float* W2    = (const float*)d_in[3];
    const float* Ws    = (const float*)d_in[4];
    const float* a_src = (const float*)d_in[5];
    const float* a_dst = (const float*)d_in[6];
    const float* bias  = (const float*)d_in[7];
    const float* W3    = (const float*)d_in[8];
    float* out = (float*)d_out;

    float *p_h, *p_hw, *p_wfold;
    cudaGetSymbolAddress((void**)&p_h,     g_h);
    cudaGetSymbolAddress((void**)&p_hw,    g_hw);
    cudaGetSymbolAddress((void**)&p_wfold, g_wfold);

    k_detect<<<1, 32>>>((const int*)ei);
    k_convert<<<256, 256>>>(ei);
    k_fold<<<(DD * OUTD + 255) / 256, 256>>>(W3);

    dim3 gg(DD / BN, (NN + BM - 1) / BM);   // (2, 157)
    // h = (x @ W1) @ W2
    k_sgemm<false><<<gg, 256>>>(NN, DD, DD, x,    W1, p_hw);
    k_sgemm<false><<<gg, 256>>>(NN, DD, DD, p_hw, W2, p_h);

    for (int l = 0; l < 6; l++) {
        k_reset<<<(NN * DD + 255) / 256, 256>>>();
        k_sgemm<false><<<gg, 256>>>(NN, DD, DD, p_h, Ws + (size_t)l * DD * DD, p_hw);
        k_nodedots<<<(NN * 32 + 255) / 256, 256>>>(a_src + l * DD, a_dst + l * DD);
        k_edge_e<<<(EE + 255) / 256, 256>>>();
        k_scatter<<<(EE * 32 + 255) / 256, 256>>>();
        k_norm<<<(NN * DD + 255) / 256, 256>>>(bias + l * DD);
    }

    // out = relu(h) @ (W3_top + W3_bot)
    k_sgemm<true><<<gg, 256>>>(NN, DD, OUTD, p_h, p_wfold, out);
}

// round 5
// speedup vs baseline: 1.4824x; 1.4824x over previous
#include <cuda_runtime.h>
#include <cuda_bf16.h>
#include <cstdint>

#define NN   20000
#define EE   320000
#define DD   256
#define OUTD 256

// ---------------- scratch (static device globals; no allocs allowed) ----------------
__device__ __align__(16) float g_h  [(size_t)NN * DD];
__device__ __align__(16) float g_hw [(size_t)NN * DD];
__device__ __align__(16) float g_acc[(size_t)NN * DD];
__device__ __align__(16) __nv_bfloat16 g_ahi[(size_t)NN * DD];
__device__ __align__(16) __nv_bfloat16 g_alo[(size_t)NN * DD];
__device__ __align__(16) __nv_bfloat16 g_bthi[DD * DD];   // B^T split hi: bt[n][k] = W[k][n]
__device__ __align__(16) __nv_bfloat16 g_btlo[DD * DD];
__device__ float g_esrc[NN];
__device__ float g_edst[NN];
__device__ float g_sum [NN];
__device__ int   g_maxord[NN];
__device__ float g_e  [EE];
__device__ int   g_src[EE];
__device__ int   g_dst[EE];
__device__ int   g_is64;

// ---------------- helpers ----------------
__device__ __forceinline__ int f2o(float f) {
    int b = __float_as_int(f);
    return b >= 0 ? b : (b ^ 0x7FFFFFFF);
}
__device__ __forceinline__ float o2f(int o) {
    return __int_as_float(o >= 0 ? o : (o ^ 0x7FFFFFFF));
}
__device__ __forceinline__ uint32_t smem_u32(const void* p) {
    uint32_t a;
    asm("{ .reg .u64 t; cvta.to.shared.u64 t, %1; cvt.u32.u64 %0, t; }" : "=r"(a) : "l"(p));
    return a;
}

// ---------------- dtype detection + index conversion ----------------
__global__ void k_detect(const int* ei32) {
    if (threadIdx.x == 0 && blockIdx.x == 0) {
        int all0 = 1;
        for (int i = 0; i < 128; i++)
            if (ei32[2 * i + 1] != 0) { all0 = 0; break; }
        g_is64 = all0;
    }
}

__global__ void k_convert(const void* ei) {
    int i = blockIdx.x * blockDim.x + threadIdx.x;
    int is64 = g_is64;
    for (; i < EE; i += gridDim.x * blockDim.x) {
        int s, t;
        if (is64) {
            const long long* p = (const long long*)ei;
            s = (int)p[i]; t = (int)p[EE + i];
        } else {
            const int* p = (const int*)ei;
            s = p[i]; t = p[EE + i];
        }
        g_src[i] = s; g_dst[i] = t;
    }
}

// ---------------- fp32 -> bf16 hi/lo split of the A operand ----------------
__global__ void k_convA(const float* __restrict__ src, int dorelu) {
    int i = blockIdx.x * blockDim.x + threadIdx.x;
    const int total = NN * DD / 8;
    if (i >= total) return;
    float4 v0 = ((const float4*)src)[2 * i];
    float4 v1 = ((const float4*)src)[2 * i + 1];
    float f[8] = {v0.x, v0.y, v0.z, v0.w, v1.x, v1.y, v1.z, v1.w};
    if (dorelu) {
        #pragma unroll
        for (int j = 0; j < 8; j++) f[j] = fmaxf(f[j], 0.f);
    }
    __nv_bfloat162 hp[4], lp[4];
    #pragma unroll
    for (int j = 0; j < 4; j++) {
        __nv_bfloat16 h0 = __float2bfloat16(f[2 * j]);
        __nv_bfloat16 h1 = __float2bfloat16(f[2 * j + 1]);
        __nv_bfloat16 l0 = __float2bfloat16(f[2 * j] - __bfloat162float(h0));
        __nv_bfloat16 l1 = __float2bfloat16(f[2 * j + 1] - __bfloat162float(h1));
        hp[j] = __halves2bfloat162(h0, h1);
        lp[j] = __halves2bfloat162(l0, l1);
    }
    *(uint4*)(g_ahi + 8 * (size_t)i) = *(uint4*)hp;
    *(uint4*)(g_alo + 8 * (size_t)i) = *(uint4*)lp;
}

// ---------------- W -> B^T bf16 hi/lo split (optionally fold W3 halves) ----------------
__global__ void k_prepB(const float* __restrict__ W, int fold) {
    int i = blockIdx.x * blockDim.x + threadIdx.x;
    if (i >= DD * DD) return;
    int n = i >> 8, k = i & 255;
    float v = W[k * DD + n];
    if (fold) v += W[(k + DD) * DD + n];
    __nv_bfloat16 h = __float2bfloat16(v);
    g_bthi[i] = h;
    g_btlo[i] = __float2bfloat16(v - __bfloat162float(h));
}

// ---------------- mma.sync bf16 GEMM: out[M,256] = A @ B ----------------
// CTA 128x128, BK=32, 256 threads (8 warps: 4 m x 2 n), cp.async double-buffered.
// 3-term bf16 split: ah*bh + ah*bl + al*bh.
#define GT 256
// stage layout (bytes): AH 8K | AL 8K | BH 8K | BL 8K, 2 stages = 64KB
#define STAGE_BYTES 32768
#define SMEM_BYTES  (2 * STAGE_BYTES)

__device__ __forceinline__ uint32_t swz(int row, int chunk) {
    return (uint32_t)(row * 64 + ((chunk ^ ((row >> 1) & 3)) << 4));
}
__device__ __forceinline__ void cpa16(uint32_t dst, const void* src, int sz) {
    asm volatile("cp.async.cg.shared.global [%0], [%1], 16, %2;"
                 :: "r"(dst), "l"(src), "r"(sz) : "memory");
}
__device__ __forceinline__ void ldsm4(uint32_t* r, uint32_t addr) {
    asm volatile("ldmatrix.sync.aligned.m8n8.x4.shared.b16 {%0,%1,%2,%3}, [%4];"
                 : "=r"(r[0]), "=r"(r[1]), "=r"(r[2]), "=r"(r[3]) : "r"(addr));
}
__device__ __forceinline__ void mma_bf16(float* d, const uint32_t* a, uint32_t b0, uint32_t b1) {
    asm volatile("mma.sync.aligned.m16n8k16.row.col.f32.bf16.bf16.f32 "
                 "{%0,%1,%2,%3}, {%4,%5,%6,%7}, {%8,%9}, {%0,%1,%2,%3};"
                 : "+f"(d[0]), "+f"(d[1]), "+f"(d[2]), "+f"(d[3])
                 : "r"(a[0]), "r"(a[1]), "r"(a[2]), "r"(a[3]), "r"(b0), "r"(b1));
}

__device__ __forceinline__ void load_stage(uint32_t sb, int stage, int kk,
                                           int rowBase, int colBase, int tid) {
    uint32_t base = sb + stage * STAGE_BYTES;
    #pragma unroll
    for (int i = 0; i < 8; i++) {
        int id = i * GT + tid;      // 0..2047
        int mat = id >> 9;          // 0:AH 1:AL 2:BH 3:BL
        int rem = id & 511;
        int row = rem >> 2, chunk = rem & 3;
        uint32_t dst = base + mat * 8192 + swz(row, chunk);
        const __nv_bfloat16* sbase =
            (mat == 0) ? g_ahi : (mat == 1) ? g_alo : (mat == 2) ? g_bthi : g_btlo;
        int grow = (mat < 2) ? (rowBase + row) : (colBase + row);
        int ok = (mat >= 2) || (grow < NN);
        int gcl = ok ? grow : 0;
        const void* src = sbase + (size_t)gcl * DD + kk * 32 + chunk * 8;
        cpa16(dst, src, ok ? 16 : 0);
    }
}

__global__ void __launch_bounds__(GT, 1)
k_gemm_mma(float* __restrict__ out, const float* __restrict__ asrc,
           const float* __restrict__ adst, int dots) {
    extern __shared__ char sm[];
    uint32_t sb = smem_u32(sm);
    const int tid = threadIdx.x, lane = tid & 31, wid = tid >> 5;
    const int warp_m = wid & 3;        // 4 m-warps of 32 rows
    const int warp_n = wid >> 2;       // 2 n-warps of 64 cols
    const int colBase = blockIdx.x * 128;
    const int rowBase = blockIdx.y * 128;

    float acc[2][8][4] = {};

    load_stage(sb, 0, 0, rowBase, colBase, tid);
    asm volatile("cp.async.commit_group;" ::: "memory");

    for (int s = 0; s < 8; s++) {
        if (s + 1 < 8) load_stage(sb, (s + 1) & 1, s + 1, rowBase, colBase, tid);
        asm volatile("cp.async.commit_group;" ::: "memory");
        asm volatile("cp.async.wait_group 1;" ::: "memory");
        __syncthreads();

        uint32_t stg = sb + (s & 1) * STAGE_BYTES;
        #pragma unroll
        for (int k16 = 0; k16 < 2; k16++) {
            int chunk = k16 * 2 + (lane >> 4);
            uint32_t ah[2][4], al[2][4];
            #pragma unroll
            for (int mf = 0; mf < 2; mf++) {
                int arow = warp_m * 32 + mf * 16 + (lane & 15);
                ldsm4(ah[mf], stg + 0    + swz(arow, chunk));
                ldsm4(al[mf], stg + 8192 + swz(arow, chunk));
            }
            uint32_t bh[4][4], bl[4][4];
            #pragma unroll
            for (int nb = 0; nb < 4; nb++) {
                int brow = warp_n * 64 + nb * 16 + (lane & 15);
                ldsm4(bh[nb], stg + 16384 + swz(brow, chunk));
                ldsm4(bl[nb], stg + 24576 + swz(brow, chunk));
            }
            #pragma unroll
            for (int mf = 0; mf < 2; mf++)
                #pragma unroll
                for (int nf = 0; nf < 8; nf++) {
                    int nb = nf >> 1, h = nf & 1;
                    float* d = acc[mf][nf];
                    mma_bf16(d, ah[mf], bh[nb][h], bh[nb][h + 2]);
                    mma_bf16(d, ah[mf], bl[nb][h], bl[nb][h + 2]);
                    mma_bf16(d, al[mf], bh[nb][h], bh[nb][h + 2]);
                }
        }
        __syncthreads();
    }

    // ---- epilogue: store C + fused attention dots ----
    #pragma unroll
    for (int mf = 0; mf < 2; mf++) {
        int r0 = rowBase + warp_m * 32 + mf * 16 + (lane >> 2);
        float s0 = 0.f, s1 = 0.f, d0 = 0.f, d1 = 0.f;
        #pragma unroll
        for (int nf = 0; nf < 8; nf++) {
            int col = colBase + warp_n * 64 + nf * 8 + (lane & 3) * 2;
            if (r0 < NN)
                *(float2*)(out + (size_t)r0 * DD + col) =
                    make_float2(acc[mf][nf][0], acc[mf][nf][1]);
            if (r0 + 8 < NN)
                *(float2*)(out + (size_t)(r0 + 8) * DD + col) =
                    make_float2(acc[mf][nf][2], acc[mf][nf][3]);
            if (dots) {
                float as0 = asrc[col], as1 = asrc[col + 1];
                float ad0 = adst[col], ad1 = adst[col + 1];
                s0 = fmaf(acc[mf][nf][0], as0, fmaf(acc[mf][nf][1], as1, s0));
                d0 = fmaf(acc[mf][nf][0], ad0, fmaf(acc[mf][nf][1], ad1, d0));
                s1 = fmaf(acc[mf][nf][2], as0, fmaf(acc[mf][nf][3], as1, s1));
                d1 = fmaf(acc[mf][nf][2], ad0, fmaf(acc[mf][nf][3], ad1, d1));
            }
        }
        if (dots) {
            #pragma unroll
            for (int o = 1; o <= 2; o <<= 1) {
                s0 += __shfl_xor_sync(0xFFFFFFFFu, s0, o);
                s1 += __shfl_xor_sync(0xFFFFFFFFu, s1, o);
                d0 += __shfl_xor_sync(0xFFFFFFFFu, d0, o);
                d1 += __shfl_xor_sync(0xFFFFFFFFu, d1, o);
            }
            if ((lane & 3) == 0) {
                if (r0 < NN)     { atomicAdd(&g_esrc[r0], s0);     atomicAdd(&g_edst[r0], d0); }
                if (r0 + 8 < NN) { atomicAdd(&g_esrc[r0 + 8], s1); atomicAdd(&g_edst[r0 + 8], d1); }
            }
        }
    }
}

// ---------------- per-layer reset (acc, sum, max, dot accumulators) ----------------
__global__ void k_reset() {
    int i = blockIdx.x * blockDim.x + threadIdx.x;
    if (i < NN * DD) g_acc[i] = 0.f;
    if (i < NN) {
        g_sum[i] = 0.f; g_maxord[i] = (int)0x80000000;
        g_esrc[i] = 0.f; g_edst[i] = 0.f;
    }
}

// ---------------- edge pass 1: e = leaky_relu(es[src]+ed[dst]); segment max ----------------
__global__ void k_edge_e() {
    int i = blockIdx.x * blockDim.x + threadIdx.x;
    if (i >= EE) return;
    int s = g_src[i], t = g_dst[i];
    float v = g_esrc[s] + g_edst[t];
    v = v > 0.f ? v : 0.2f * v;
    g_e[i] = v;
    atomicMax(&g_maxord[t], f2o(v));
}

// ---------------- edge pass 2: ee = exp(e-m); scatter ee*hw[src]; sum ee ----------------
__global__ void k_scatter() {
    int g = blockIdx.x * blockDim.x + threadIdx.x;
    int eid = g >> 5, lane = g & 31;
    if (eid >= EE) return;
    int s = g_src[eid], t = g_dst[eid];
    float ee = __expf(g_e[eid] - o2f(g_maxord[t]));
    if (lane == 0) atomicAdd(&g_sum[t], ee);
    const float4* hs = (const float4*)(g_hw + (size_t)s * DD);
    float* ad = g_acc + (size_t)t * DD;
    #pragma unroll
    for (int i = lane; i < DD / 4; i += 32) {
        float4 v = hs[i];
        asm volatile("red.global.add.v4.f32 [%0], {%1, %2, %3, %4};"
                     :: "l"(ad + i * 4),
                        "f"(ee * v.x), "f"(ee * v.y), "f"(ee * v.z), "f"(ee * v.w)
                     : "memory");
    }
}

// ---------------- normalize + bias: h = acc/denom + b ----------------
__global__ void k_norm(const float* __restrict__ b) {
    int i = blockIdx.x * blockDim.x + threadIdx.x;
    if (i >= NN * DD) return;
    int n = i >> 8, d = i & 255;
    float s = g_sum[n];
    float v = (s > 0.f) ? g_acc[i] / s : 0.f;
    g_h[i] = v + b[d];
}

// ---------------- launch ----------------
extern "C" void kernel_launch(void* const* d_in, const int* in_sizes, int n_in,
                              void* d_out, int out_size) {
    const float* x     = (const float*)d_in[0];
    const void*  ei    = d_in[1];
    const float* W1    = (const float*)d_in[2];
    const float* W2    = (const float*)d_in[3];
    const float* Ws    = (const float*)d_in[4];
    const float* a_src = (const float*)d_in[5];
    const float* a_dst = (const float*)d_in[6];
    const float* bias  = (const float*)d_in[7];
    const float* W3    = (const float*)d_in[8];
    float* out = (float*)d_out;

    float *p_h, *p_hw;
    cudaGetSymbolAddress((void**)&p_h,  g_h);
    cudaGetSymbolAddress((void**)&p_hw, g_hw);

    cudaFuncSetAttribute(k_gemm_mma, cudaFuncAttributeMaxDynamicSharedMemorySize, SMEM_BYTES);

    k_detect<<<1, 32>>>((const int*)ei);
    k_convert<<<256, 256>>>(ei);

    const int CAB = (NN * DD / 8 + 255) / 256;
    const int PBB = (DD * DD + 255) / 256;
    dim3 gg(2, (NN + 127) / 128);   // (2, 157)

    // hw = x @ W1
    k_convA<<<CAB, 256>>>(x, 0);
    k_prepB<<<PBB, 256>>>(W1, 0);
    k_gemm_mma<<<gg, GT, SMEM_BYTES>>>(p_hw, nullptr, nullptr, 0);
    // h = hw @ W2
    k_convA<<<CAB, 256>>>(p_hw, 0);
    k_prepB<<<PBB, 256>>>(W2, 0);
    k_gemm_mma<<<gg, GT, SMEM_BYTES>>>(p_h, nullptr, nullptr, 0);

    for (int l = 0; l < 6; l++) {
        k_reset<<<(NN * DD + 255) / 256, 256>>>();
        k_convA<<<CAB, 256>>>(p_h, 0);
        k_prepB<<<PBB, 256>>>(Ws + (size_t)l * DD * DD, 0);
        k_gemm_mma<<<gg, GT, SMEM_BYTES>>>(p_hw, a_src + l * DD, a_dst + l * DD, 1);
        k_edge_e<<<(EE + 255) / 256, 256>>>();
        k_scatter<<<(EE * 32 + 255) / 256, 256>>>();
        k_norm<<<(NN * DD + 255) / 256, 256>>>(bias + l * DD);
    }

    // out = relu(h) @ (W3_top + W3_bot)
    k_convA<<<CAB, 256>>>(p_h, 1);
    k_prepB<<<PBB, 256>>>(W3, 1);
    k_gemm_mma<<<gg, GT, SMEM_BYTES>>>(out, nullptr, nullptr, 0);
}

// round 7
// speedup vs baseline: 1.5409x; 1.0395x over previous
#include <cuda_runtime.h>
#include <cuda_bf16.h>
#include <cstdint>

#define NN   20000
#define EE   320000
#define DD   256

// ---------------- scratch (static device globals; no allocs allowed) ----------------
__device__ __align__(16) float g_hw[(size_t)NN * DD];
__device__ __align__(16) __nv_bfloat16 g_ahi [(size_t)NN * DD];   // split buffer S0
__device__ __align__(16) __nv_bfloat16 g_alo [(size_t)NN * DD];
__device__ __align__(16) __nv_bfloat16 g_a2hi[(size_t)NN * DD];   // split buffer S1
__device__ __align__(16) __nv_bfloat16 g_a2lo[(size_t)NN * DD];
__device__ __align__(16) __nv_bfloat16 g_bhi[9 * DD * DD];        // 9 weight slots, B^T split
__device__ __align__(16) __nv_bfloat16 g_blo[9 * DD * DD];
__device__ float g_esp[4 * NN];   // attention-dot partials (2 colCTAs x 2 warp_n)
__device__ float g_edp[4 * NN];
__device__ int g_srcA[EE], g_dstA[EE], g_csrc[EE];
__device__ int g_deg[NN], g_rowptr[NN + 1], g_cursor[NN];
__device__ int g_is64;

// ---------------- helpers ----------------
__device__ __forceinline__ uint32_t smem_u32(const void* p) {
    uint32_t a;
    asm("{ .reg .u64 t; cvta.to.shared.u64 t, %1; cvt.u32.u64 %0, t; }" : "=r"(a) : "l"(p));
    return a;
}

// ---------------- dtype detect / convert+count / scan / fill ----------------
__global__ void k_detect(const int* ei32) {
    if (threadIdx.x == 0 && blockIdx.x == 0) {
        int all0 = 1;
        for (int i = 0; i < 128; i++)
            if (ei32[2 * i + 1] != 0) { all0 = 0; break; }
        g_is64 = all0;
    }
}
__global__ void k_deg0() {
    int i = blockIdx.x * blockDim.x + threadIdx.x;
    if (i < NN) g_deg[i] = 0;
}
__global__ void k_convert(const void* ei) {
    int i = blockIdx.x * blockDim.x + threadIdx.x;
    int is64 = g_is64;
    for (; i < EE; i += gridDim.x * blockDim.x) {
        int s, t;
        if (is64) {
            const long long* p = (const long long*)ei;
            s = (int)p[i]; t = (int)p[EE + i];
        } else {
            const int* p = (const int*)ei;
            s = p[i]; t = p[EE + i];
        }
        g_srcA[i] = s; g_dstA[i] = t;
        atomicAdd(&g_deg[t], 1);
    }
}
__global__ void k_scan() {   // single block, 1024 threads
    __shared__ int part[1024];
    const int CH = (NN + 1023) / 1024;     // 20
    int t = threadIdx.x;
    int lo = t * CH, hi = min(lo + CH, NN);
    int s = 0;
    for (int i = lo; i < hi; i++) s += g_deg[i];
    part[t] = s;
    __syncthreads();
    for (int off = 1; off < 1024; off <<= 1) {
        int v = (t >= off) ? part[t - off] : 0;
        __syncthreads();
        part[t] += v;
        __syncthreads();
    }
    int excl = (t == 0) ? 0 : part[t - 1];
    for (int i = lo; i < hi; i++) {
        g_rowptr[i] = excl; g_cursor[i] = excl;
        excl += g_deg[i];
    }
    if (t == 0) g_rowptr[NN] = EE;
}
__global__ void k_fill() {
    int i = blockIdx.x * blockDim.x + threadIdx.x;
    for (; i < EE; i += gridDim.x * blockDim.x) {
        int pos = atomicAdd(&g_cursor[g_dstA[i]], 1);
        g_csrc[pos] = g_srcA[i];
    }
}

// ---------------- fp32 -> bf16 hi/lo split of x ----------------
__global__ void k_convA(const float* __restrict__ src) {
    int i = blockIdx.x * blockDim.x + threadIdx.x;
    const int total = NN * DD / 8;
    if (i >= total) return;
    float4 v0 = ((const float4*)src)[2 * i];
    float4 v1 = ((const float4*)src)[2 * i + 1];
    float f[8] = {v0.x, v0.y, v0.z, v0.w, v1.x, v1.y, v1.z, v1.w};
    __nv_bfloat162 hp[4], lp[4];
    #pragma unroll
    for (int j = 0; j < 4; j++) {
        __nv_bfloat16 h0 = __float2bfloat16(f[2 * j]);
        __nv_bfloat16 h1 = __float2bfloat16(f[2 * j + 1]);
        hp[j] = __halves2bfloat162(h0, h1);
        lp[j] = __halves2bfloat162(__float2bfloat16(f[2 * j] - __bfloat162float(h0)),
                                   __float2bfloat16(f[2 * j + 1] - __bfloat162float(h1)));
    }
    *(uint4*)(g_ahi + 8 * (size_t)i) = *(uint4*)hp;
    *(uint4*)(g_alo + 8 * (size_t)i) = *(uint4*)lp;
}

// ---------------- all 9 weights -> B^T bf16 hi/lo split (slot 8 folds W3) ----------------
__global__ void k_prepAllB(const float* __restrict__ W1, const float* __restrict__ W2,
                           const float* __restrict__ Ws, const float* __restrict__ W3) {
    int i = blockIdx.x * blockDim.x + threadIdx.x;
    if (i >= 9 * DD * DD) return;
    int slot = i >> 16, idx = i & 65535;
    int n = idx >> 8, k = idx & 255;
    float v;
    if (slot == 0)      v = W1[k * DD + n];
    else if (slot == 1) v = W2[k * DD + n];
    else if (slot < 8)  v = Ws[(size_t)(slot - 2) * DD * DD + k * DD + n];
    else                v = W3[k * DD + n] + W3[(k + DD) * DD + n];
    __nv_bfloat16 h = __float2bfloat16(v);
    g_bhi[i] = h;
    g_blo[i] = __float2bfloat16(v - __bfloat162float(h));
}

// ---------------- mma.sync bf16 GEMM: out[M,256] = A @ B ----------------
#define GT 256
#define STAGE_BYTES 32768
#define SMEM_BYTES  (2 * STAGE_BYTES)

__device__ __forceinline__ uint32_t swz(int row, int chunk) {
    return (uint32_t)(row * 64 + ((chunk ^ ((row >> 1) & 3)) << 4));
}
__device__ __forceinline__ void cpa16(uint32_t dst, const void* src, int sz) {
    asm volatile("cp.async.cg.shared.global [%0], [%1], 16, %2;"
                 :: "r"(dst), "l"(src), "r"(sz) : "memory");
}
__device__ __forceinline__ void ldsm4(uint32_t* r, uint32_t addr) {
    asm volatile("ldmatrix.sync.aligned.m8n8.x4.shared.b16 {%0,%1,%2,%3}, [%4];"
                 : "=r"(r[0]), "=r"(r[1]), "=r"(r[2]), "=r"(r[3]) : "r"(addr));
}
__device__ __forceinline__ void mma_bf16(float* d, const uint32_t* a, uint32_t b0, uint32_t b1) {
    asm volatile("mma.sync.aligned.m16n8k16.row.col.f32.bf16.bf16.f32 "
                 "{%0,%1,%2,%3}, {%4,%5,%6,%7}, {%8,%9}, {%0,%1,%2,%3};"
                 : "+f"(d[0]), "+f"(d[1]), "+f"(d[2]), "+f"(d[3])
                 : "r"(a[0]), "r"(a[1]), "r"(a[2]), "r"(a[3]), "r"(b0), "r"(b1));
}

__device__ __forceinline__ void load_stage(uint32_t sb, int stage, int kk,
                                           int rowBase, int colBase, int tid,
                                           const __nv_bfloat16* ahi, const __nv_bfloat16* alo,
                                           const __nv_bfloat16* bhi, const __nv_bfloat16* blo) {
    uint32_t base = sb + stage * STAGE_BYTES;
    #pragma unroll
    for (int i = 0; i < 8; i++) {
        int id = i * GT + tid;
        int mat = id >> 9;
        int rem = id & 511;
        int row = rem >> 2, chunk = rem & 3;
        uint32_t dst = base + mat * 8192 + swz(row, chunk);
        const __nv_bfloat16* sbase =
            (mat == 0) ? ahi : (mat == 1) ? alo : (mat == 2) ? bhi : blo;
        int grow = (mat < 2) ? (rowBase + row) : (colBase + row);
        int ok = (mat >= 2) || (grow < NN);
        int gcl = ok ? grow : 0;
        cpa16(dst, sbase + (size_t)gcl * DD + kk * 32 + chunk * 8, ok ? 16 : 0);
    }
}

__global__ void __launch_bounds__(GT, 1)
k_gemm_mma(float* __restrict__ out,
           const __nv_bfloat16* __restrict__ ahi, const __nv_bfloat16* __restrict__ alo,
           const __nv_bfloat16* __restrict__ bhi, const __nv_bfloat16* __restrict__ blo,
           __nv_bfloat16* __restrict__ ehi, __nv_bfloat16* __restrict__ elo,
           const float* __restrict__ asrc, const float* __restrict__ adst, int dots) {
    extern __shared__ char sm[];
    uint32_t sb = smem_u32(sm);
    const int tid = threadIdx.x, lane = tid & 31, wid = tid >> 5;
    const int warp_m = wid & 3;
    const int warp_n = wid >> 2;
    const int colBase = blockIdx.x * 128;
    const int rowBase = blockIdx.y * 128;

    float acc[2][8][4] = {};

    load_stage(sb, 0, 0, rowBase, colBase, tid, ahi, alo, bhi, blo);
    asm volatile("cp.async.commit_group;" ::: "memory");

    for (int s = 0; s < 8; s++) {
        if (s + 1 < 8) load_stage(sb, (s + 1) & 1, s + 1, rowBase, colBase, tid, ahi, alo, bhi, blo);
        asm volatile("cp.async.commit_group;" ::: "memory");
        asm volatile("cp.async.wait_group 1;" ::: "memory");
        __syncthreads();

        uint32_t stg = sb + (s & 1) * STAGE_BYTES;
        #pragma unroll
        for (int k16 = 0; k16 < 2; k16++) {
            int chunk = k16 * 2 + (lane >> 4);
            uint32_t ah[2][4], al[2][4];
            #pragma unroll
            for (int mf = 0; mf < 2; mf++) {
                int arow = warp_m * 32 + mf * 16 + (lane & 15);
                ldsm4(ah[mf], stg + 0    + swz(arow, chunk));
                ldsm4(al[mf], stg + 8192 + swz(arow, chunk));
            }
            uint32_t bhr[4][4], blr[4][4];
            #pragma unroll
            for (int nb = 0; nb < 4; nb++) {
                int brow = warp_n * 64 + nb * 16 + (lane & 15);
                ldsm4(bhr[nb], stg + 16384 + swz(brow, chunk));
                ldsm4(blr[nb], stg + 24576 + swz(brow, chunk));
            }
            #pragma unroll
            for (int mf = 0; mf < 2; mf++)
                #pragma unroll
                for (int nf = 0; nf < 8; nf++) {
                    int nb = nf >> 1, h = nf & 1;
                    float* d = acc[mf][nf];
                    mma_bf16(d, ah[mf], bhr[nb][h], bhr[nb][h + 2]);
                    mma_bf16(d, ah[mf], blr[nb][h], blr[nb][h + 2]);
                    mma_bf16(d, al[mf], bhr[nb][h], bhr[nb][h + 2]);
                }
        }
        __syncthreads();
    }

    // ---- epilogue: store C (+ optional split emit, + attention-dot partials) ----
    const int slot = (blockIdx.x * 2 + warp_n) * NN;
    #pragma unroll
    for (int mf = 0; mf < 2; mf++) {
        int r0 = rowBase + warp_m * 32 + mf * 16 + (lane >> 2);
        float s0 = 0.f, s1 = 0.f, d0 = 0.f, d1 = 0.f;
        #pragma unroll
        for (int nf = 0; nf < 8; nf++) {
            int col = colBase + warp_n * 64 + nf * 8 + (lane & 3) * 2;
            #pragma unroll
            for (int half = 0; half < 2; half++) {
                int r = r0 + half * 8;
                if (r < NN) {
                    float v0 = acc[mf][nf][2 * half], v1 = acc[mf][nf][2 * half + 1];
                    *(float2*)(out + (size_t)r * DD + col) = make_float2(v0, v1);
                    if (ehi) {
                        __nv_bfloat16 h0 = __float2bfloat16(v0);
                        __nv_bfloat16 h1 = __float2bfloat16(v1);
                        *(__nv_bfloat162*)(ehi + (size_t)r * DD + col) = __halves2bfloat162(h0, h1);
                        *(__nv_bfloat162*)(elo + (size_t)r * DD + col) = __halves2bfloat162(
                            __float2bfloat16(v0 - __bfloat162float(h0)),
                            __float2bfloat16(v1 - __bfloat162float(h1)));
                    }
                }
            }
            if (dots) {
                float as0 = asrc[col], as1 = asrc[col + 1];
                float ad0 = adst[col], ad1 = adst[col + 1];
                s0 = fmaf(acc[mf][nf][0], as0, fmaf(acc[mf][nf][1], as1, s0));
                d0 = fmaf(acc[mf][nf][0], ad0, fmaf(acc[mf][nf][1], ad1, d0));
                s1 = fmaf(acc[mf][nf][2], as0, fmaf(acc[mf][nf][3], as1, s1));
                d1 = fmaf(acc[mf][nf][2], ad0, fmaf(acc[mf][nf][3], ad1, d1));
            }
        }
        if (dots) {
            #pragma unroll
            for (int o = 1; o <= 2; o <<= 1) {
                s0 += __shfl_xor_sync(0xFFFFFFFFu, s0, o);
                s1 += __shfl_xor_sync(0xFFFFFFFFu, s1, o);
                d0 += __shfl_xor_sync(0xFFFFFFFFu, d0, o);
                d1 += __shfl_xor_sync(0xFFFFFFFFu, d1, o);
            }
            if ((lane & 3) == 0) {   // plain stores: partial per (colCTA, warp_n); no atomics
                if (r0 < NN)     { g_esp[slot + r0] = s0;     g_edp[slot + r0] = d0; }
                if (r0 + 8 < NN) { g_esp[slot + r0 + 8] = s1; g_edp[slot + r0 + 8] = d1; }
            }
        }
    }
}

// ---------------- fused GAT aggregate: softmax over in-edges + gather + bias + split emit ----------------
__device__ __forceinline__ float esum(const float* p, int s) {
    return p[s] + p[NN + s] + p[2 * NN + s] + p[3 * NN + s];
}

__global__ void __launch_bounds__(256)
k_gat(const float* __restrict__ bias, int dorelu) {
    int wid = threadIdx.x >> 5, lane = threadIdx.x & 31;
    int n = blockIdx.x * 8 + wid;
    if (n >= NN) return;
    int start = g_rowptr[n], end = g_rowptr[n + 1];
    float ed = esum(g_edp, n);

    // pass 1: segment max
    float m = -3.4e38f;
    for (int j = start + lane; j < end; j += 32) {
        float v = esum(g_esp, g_csrc[j]) + ed;
        v = v > 0.f ? v : 0.2f * v;
        m = fmaxf(m, v);
    }
    #pragma unroll
    for (int o = 16; o > 0; o >>= 1) m = fmaxf(m, __shfl_xor_sync(0xFFFFFFFFu, m, o));

    // pass 2: exp-weighted gather (all lanes see same ee; lanes split the 256 cols)
    float acc[8] = {};
    float sum = 0.f;
    for (int j = start; j < end; j++) {
        int s = g_csrc[j];
        float v = esum(g_esp, s) + ed;
        v = v > 0.f ? v : 0.2f * v;
        float ee = __expf(v - m);
        sum += ee;
        const float4* row = (const float4*)(g_hw + (size_t)s * DD);
        float4 a = row[lane], b = row[lane + 32];
        acc[0] = fmaf(ee, a.x, acc[0]); acc[1] = fmaf(ee, a.y, acc[1]);
        acc[2] = fmaf(ee, a.z, acc[2]); acc[3] = fmaf(ee, a.w, acc[3]);
        acc[4] = fmaf(ee, b.x, acc[4]); acc[5] = fmaf(ee, b.y, acc[5]);
        acc[6] = fmaf(ee, b.z, acc[6]); acc[7] = fmaf(ee, b.w, acc[7]);
    }
    float inv = (end > start) ? 1.0f / sum : 0.f;

    float4 b0 = ((const float4*)bias)[lane];
    float4 b1 = ((const float4*)bias)[lane + 32];
    float o[8] = {acc[0] * inv + b0.x, acc[1] * inv + b0.y,
                  acc[2] * inv + b0.z, acc[3] * inv + b0.w,
                  acc[4] * inv + b1.x, acc[5] * inv + b1.y,
                  acc[6] * inv + b1.z, acc[7] * inv + b1.w};
    if (dorelu) {
        #pragma unroll
        for (int j = 0; j < 8; j++) o[j] = fmaxf(o[j], 0.f);
    }
    // emit bf16 hi/lo split: cols 4*lane.. and 128+4*lane..
    __nv_bfloat162 hp[4], lp[4];
    #pragma unroll
    for (int j = 0; j < 4; j++) {
        int j0 = (j >> 1) * 4 + (j & 1) * 2;   // 0,2,4,6 -> pairs (0,1)(2,3)(4,5)(6,7)
        __nv_bfloat16 h0 = __float2bfloat16(o[2 * j]);
        __nv_bfloat16 h1 = __float2bfloat16(o[2 * j + 1]);
        hp[j] = __halves2bfloat162(h0, h1);
        lp[j] = __halves2bfloat162(__float2bfloat16(o[2 * j] - __bfloat162float(h0)),
                                   __float2bfloat16(o[2 * j + 1] - __bfloat162float(h1)));
        (void)j0;
    }
    __nv_bfloat16* dh = g_ahi + (size_t)n * DD;
    __nv_bfloat16* dl = g_alo + (size_t)n * DD;
    *(uint2*)(dh + 4 * lane)       = make_uint2(((uint2*)hp)[0].x, ((uint2*)hp)[0].y);
    *(uint2*)(dh + 128 + 4 * lane) = make_uint2(((uint2*)hp)[1].x, ((uint2*)hp)[1].y);
    *(uint2*)(dl + 4 * lane)       = make_uint2(((uint2*)lp)[0].x, ((uint2*)lp)[0].y);
    *(uint2*)(dl + 128 + 4 * lane) = make_uint2(((uint2*)lp)[1].x, ((uint2*)lp)[1].y);
}

// ---------------- launch ----------------
extern "C" void kernel_launch(void* const* d_in, const int* in_sizes, int n_in,
                              void* d_out, int out_size) {
    const float* x     = (const float*)d_in[0];
    const void*  ei    = d_in[1];
    const float* W1    = (const float*)d_in[2];
    const float* W2    = (const float*)d_in[3];
    const float* Ws    = (const float*)d_in[4];
    const float* a_src = (const float*)d_in[5];
    const float* a_dst = (const float*)d_in[6];
    const float* bias  = (const float*)d_in[7];
    const float* W3    = (const float*)d_in[8];
    float* out = (float*)d_out;

    float* p_hw;
    __nv_bfloat16 *p_ahi, *p_alo, *p_a2hi, *p_a2lo, *p_bhi, *p_blo;
    cudaGetSymbolAddress((void**)&p_hw,   g_hw);
    cudaGetSymbolAddress((void**)&p_ahi,  g_ahi);
    cudaGetSymbolAddress((void**)&p_alo,  g_alo);
    cudaGetSymbolAddress((void**)&p_a2hi, g_a2hi);
    cudaGetSymbolAddress((void**)&p_a2lo, g_a2lo);
    cudaGetSymbolAddress((void**)&p_bhi,  g_bhi);
    cudaGetSymbolAddress((void**)&p_blo,  g_blo);

    cudaFuncSetAttribute(k_gemm_mma, cudaFuncAttributeMaxDynamicSharedMemorySize, SMEM_BYTES);

    // one-time: indices, CSR, x split, all weight splits
    k_detect<<<1, 32>>>((const int*)ei);
    k_deg0<<<(NN + 255) / 256, 256>>>();
    k_convert<<<256, 256>>>(ei);
    k_scan<<<1, 1024>>>();
    k_fill<<<256, 256>>>();
    k_convA<<<(NN * DD / 8 + 255) / 256, 256>>>(x);
    k_prepAllB<<<(9 * DD * DD + 255) / 256, 256>>>(W1, W2, Ws, W3);

    dim3 gg(2, (NN + 127) / 128);
    const int BW = DD * DD;

    // hw = x@W1 (emit split to S1); h = hw@W2 (emit split to S0)
    k_gemm_mma<<<gg, GT, SMEM_BYTES>>>(p_hw, p_ahi, p_alo, p_bhi, p_blo,
                                       p_a2hi, p_a2lo, nullptr, nullptr, 0);
    k_gemm_mma<<<gg, GT, SMEM_BYTES>>>(p_hw, p_a2hi, p_a2lo, p_bhi + BW, p_blo + BW,
                                       p_ahi, p_alo, nullptr, nullptr, 0);

    for (int l = 0; l < 6; l++) {
        k_gemm_mma<<<gg, GT, SMEM_BYTES>>>(p_hw, p_ahi, p_alo,
                                           p_bhi + (size_t)(2 + l) * BW, p_blo + (size_t)(2 + l) * BW,
                                           nullptr, nullptr, a_src + l * DD, a_dst + l * DD, 1);
        k_gat<<<(NN + 7) / 8, 256>>>(bias + l * DD, l == 5 ? 1 : 0);
    }

    // out = relu(h) @ (W3_top + W3_bot)   (relu folded into last k_gat's split)
    k_gemm_mma<<<gg, GT, SMEM_BYTES>>>(out, p_ahi, p_alo, p_bhi + 8 * BW, p_blo + 8 * BW,
                                       nullptr, nullptr, nullptr, nullptr, 0);
}

// round 8
// speedup vs baseline: 2.5476x; 1.6533x over previous
#include <cuda_runtime.h>
#include <cuda_bf16.h>
#include <cstdint>

#define NN   20000
#define EE   320000
#define DD   256

// ---------------- scratch (static device globals; no allocs allowed) ----------------
__device__ __align__(16) float g_hw[(size_t)NN * DD];
__device__ __align__(16) __nv_bfloat16 g_ahi [(size_t)NN * DD];   // split buffer S0
__device__ __align__(16) __nv_bfloat16 g_alo [(size_t)NN * DD];
__device__ __align__(16) __nv_bfloat16 g_a2hi[(size_t)NN * DD];   // split buffer S1
__device__ __align__(16) __nv_bfloat16 g_a2lo[(size_t)NN * DD];
__device__ __align__(16) __nv_bfloat16 g_bhi[9 * DD * DD];        // 9 weight slots, B^T split
__device__ __align__(16) __nv_bfloat16 g_blo[9 * DD * DD];
__device__ float g_esp[4 * NN];   // attention-dot partials (2 colCTAs x 2 warp_n)
__device__ float g_edp[4 * NN];
__device__ float g_est[NN];       // summed dot totals
__device__ float g_edt[NN];
__device__ int g_srcA[EE], g_dstA[EE], g_csrc[EE];
__device__ __align__(16) int g_deg[NN];
__device__ int g_rowptr[NN + 1], g_cursor[NN];
__device__ int g_is64;

// ---------------- helpers ----------------
__device__ __forceinline__ uint32_t smem_u32(const void* p) {
    uint32_t a;
    asm("{ .reg .u64 t; cvta.to.shared.u64 t, %1; cvt.u32.u64 %0, t; }" : "=r"(a) : "l"(p));
    return a;
}

// ---------------- parallel dtype detect ----------------
__global__ void k_detect(const int* ei32) {
    __shared__ int anynz;
    int t = threadIdx.x;                     // 128 threads
    if (t == 0) anynz = 0;
    __syncthreads();
    int nz = (ei32[2 * t + 1] != 0);
    if (__any_sync(0xFFFFFFFFu, nz) && (t & 31) == 0) atomicOr(&anynz, 1);
    __syncthreads();
    if (t == 0) g_is64 = anynz ? 0 : 1;      // all high words zero => int64
}

// ---------------- convert + degree count ----------------
__global__ void k_convert(const void* ei) {
    int i = blockIdx.x * blockDim.x + threadIdx.x;
    int is64 = g_is64;
    for (; i < EE; i += gridDim.x * blockDim.x) {
        int s, t;
        if (is64) {
            const long long* p = (const long long*)ei;
            s = (int)p[i]; t = (int)p[EE + i];
        } else {
            const int* p = (const int*)ei;
            s = p[i]; t = p[EE + i];
        }
        g_srcA[i] = s; g_dstA[i] = t;
        atomicAdd(&g_deg[t], 1);
    }
}

// ---------------- single-block warp-shuffle scan (NN = 1000 * 20) ----------------
__global__ void k_scan() {
    __shared__ int wsum[32];
    int t = threadIdx.x, lane = t & 31, w = t >> 5;
    int loc[20];
    int s = 0;
    if (t < 1000) {
        const int4* p = (const int4*)(g_deg + t * 20);
        #pragma unroll
        for (int i = 0; i < 5; i++) {
            int4 v = p[i];
            loc[4 * i]     = s; s += v.x;
            loc[4 * i + 1] = s; s += v.y;
            loc[4 * i + 2] = s; s += v.z;
            loc[4 * i + 3] = s; s += v.w;
        }
    }
    int inc = s;
    #pragma unroll
    for (int o = 1; o < 32; o <<= 1) {
        int v = __shfl_up_sync(0xFFFFFFFFu, inc, o);
        if (lane >= o) inc += v;
    }
    if (lane == 31) wsum[w] = inc;
    __syncthreads();
    if (w == 0) {
        int v = wsum[lane];
        int wi = v;
        #pragma unroll
        for (int o = 1; o < 32; o <<= 1) {
            int u = __shfl_up_sync(0xFFFFFFFFu, wi, o);
            if (lane >= o) wi += u;
        }
        wsum[lane] = wi - v;   // exclusive
    }
    __syncthreads();
    int excl = wsum[w] + (inc - s);
    if (t < 1000) {
        int base = t * 20;
        #pragma unroll
        for (int i = 0; i < 20; i++) {
            int r = excl + loc[i];
            g_rowptr[base + i] = r;
            g_cursor[base + i] = r;
        }
    }
    if (t == 0) g_rowptr[NN] = EE;
}

__global__ void k_fill() {
    int i = blockIdx.x * blockDim.x + threadIdx.x;
    for (; i < EE; i += gridDim.x * blockDim.x) {
        int pos = atomicAdd(&g_cursor[g_dstA[i]], 1);
        g_csrc[pos] = g_srcA[i];
    }
}

// ---------------- fp32 -> bf16 hi/lo split of x ----------------
__global__ void k_convA(const float* __restrict__ src) {
    int i = blockIdx.x * blockDim.x + threadIdx.x;
    const int total = NN * DD / 8;
    if (i >= total) return;
    float4 v0 = ((const float4*)src)[2 * i];
    float4 v1 = ((const float4*)src)[2 * i + 1];
    float f[8] = {v0.x, v0.y, v0.z, v0.w, v1.x, v1.y, v1.z, v1.w};
    __nv_bfloat162 hp[4], lp[4];
    #pragma unroll
    for (int j = 0; j < 4; j++) {
        __nv_bfloat16 h0 = __float2bfloat16(f[2 * j]);
        __nv_bfloat16 h1 = __float2bfloat16(f[2 * j + 1]);
        hp[j] = __halves2bfloat162(h0, h1);
        lp[j] = __halves2bfloat162(__float2bfloat16(f[2 * j] - __bfloat162float(h0)),
                                   __float2bfloat16(f[2 * j + 1] - __bfloat162float(h1)));
    }
    *(uint4*)(g_ahi + 8 * (size_t)i) = *(uint4*)hp;
    *(uint4*)(g_alo + 8 * (size_t)i) = *(uint4*)lp;
}

// ---------------- all 9 weights -> B^T bf16 hi/lo split (slot 8 folds W3) ----------------
__global__ void k_prepAllB(const float* __restrict__ W1, const float* __restrict__ W2,
                           const float* __restrict__ Ws, const float* __restrict__ W3) {
    int i = blockIdx.x * blockDim.x + threadIdx.x;
    if (i >= 9 * DD * DD) return;
    int slot = i >> 16, idx = i & 65535;
    int n = idx >> 8, k = idx & 255;
    float v;
    if (slot == 0)      v = W1[k * DD + n];
    else if (slot == 1) v = W2[k * DD + n];
    else if (slot < 8)  v = Ws[(size_t)(slot - 2) * DD * DD + k * DD + n];
    else                v = W3[k * DD + n] + W3[(k + DD) * DD + n];
    __nv_bfloat16 h = __float2bfloat16(v);
    g_bhi[i] = h;
    g_blo[i] = __float2bfloat16(v - __bfloat162float(h));
}

// ---------------- mma.sync bf16 GEMM: out[M,256] = A @ B ----------------
#define GT 256
#define STAGE_BYTES 32768
#define SMEM_BYTES  (2 * STAGE_BYTES)

__device__ __forceinline__ uint32_t swz(int row, int chunk) {
    return (uint32_t)(row * 64 + ((chunk ^ ((row >> 1) & 3)) << 4));
}
__device__ __forceinline__ void cpa16(uint32_t dst, const void* src, int sz) {
    asm volatile("cp.async.cg.shared.global [%0], [%1], 16, %2;"
                 :: "r"(dst), "l"(src), "r"(sz) : "memory");
}
__device__ __forceinline__ void ldsm4(uint32_t* r, uint32_t addr) {
    asm volatile("ldmatrix.sync.aligned.m8n8.x4.shared.b16 {%0,%1,%2,%3}, [%4];"
                 : "=r"(r[0]), "=r"(r[1]), "=r"(r[2]), "=r"(r[3]) : "r"(addr));
}
__device__ __forceinline__ void mma_bf16(float* d, const uint32_t* a, uint32_t b0, uint32_t b1) {
    asm volatile("mma.sync.aligned.m16n8k16.row.col.f32.bf16.bf16.f32 "
                 "{%0,%1,%2,%3}, {%4,%5,%6,%7}, {%8,%9}, {%0,%1,%2,%3};"
                 : "+f"(d[0]), "+f"(d[1]), "+f"(d[2]), "+f"(d[3])
                 : "r"(a[0]), "r"(a[1]), "r"(a[2]), "r"(a[3]), "r"(b0), "r"(b1));
}

__device__ __forceinline__ void load_stage(uint32_t sb, int stage, int kk,
                                           int rowBase, int colBase, int tid,
                                           const __nv_bfloat16* ahi, const __nv_bfloat16* alo,
                                           const __nv_bfloat16* bhi, const __nv_bfloat16* blo) {
    uint32_t base = sb + stage * STAGE_BYTES;
    #pragma unroll
    for (int i = 0; i < 8; i++) {
        int id = i * GT + tid;
        int mat = id >> 9;
        int rem = id & 511;
        int row = rem >> 2, chunk = rem & 3;
        uint32_t dst = base + mat * 8192 + swz(row, chunk);
        const __nv_bfloat16* sbase =
            (mat == 0) ? ahi : (mat == 1) ? alo : (mat == 2) ? bhi : blo;
        int grow = (mat < 2) ? (rowBase + row) : (colBase + row);
        int ok = (mat >= 2) || (grow < NN);
        int gcl = ok ? grow : 0;
        cpa16(dst, sbase + (size_t)gcl * DD + kk * 32 + chunk * 8, ok ? 16 : 0);
    }
}

__global__ void __launch_bounds__(GT, 1)
k_gemm_mma(float* __restrict__ out,
           const __nv_bfloat16* __restrict__ ahi, const __nv_bfloat16* __restrict__ alo,
           const __nv_bfloat16* __restrict__ bhi, const __nv_bfloat16* __restrict__ blo,
           __nv_bfloat16* __restrict__ ehi, __nv_bfloat16* __restrict__ elo,
           const float* __restrict__ asrc, const float* __restrict__ adst, int dots) {
    extern __shared__ char sm[];
    uint32_t sb = smem_u32(sm);
    const int tid = threadIdx.x, lane = tid & 31, wid = tid >> 5;
    const int warp_m = wid & 3;
    const int warp_n = wid >> 2;
    const int colBase = blockIdx.x * 128;
    const int rowBase = blockIdx.y * 128;

    float acc[2][8][4] = {};

    load_stage(sb, 0, 0, rowBase, colBase, tid, ahi, alo, bhi, blo);
    asm volatile("cp.async.commit_group;" ::: "memory");

    for (int s = 0; s < 8; s++) {
        if (s + 1 < 8) load_stage(sb, (s + 1) & 1, s + 1, rowBase, colBase, tid, ahi, alo, bhi, blo);
        asm volatile("cp.async.commit_group;" ::: "memory");
        asm volatile("cp.async.wait_group 1;" ::: "memory");
        __syncthreads();

        uint32_t stg = sb + (s & 1) * STAGE_BYTES;
        #pragma unroll
        for (int k16 = 0; k16 < 2; k16++) {
            int chunk = k16 * 2 + (lane >> 4);
            uint32_t ah[2][4], al[2][4];
            #pragma unroll
            for (int mf = 0; mf < 2; mf++) {
                int arow = warp_m * 32 + mf * 16 + (lane & 15);
                ldsm4(ah[mf], stg + 0    + swz(arow, chunk));
                ldsm4(al[mf], stg + 8192 + swz(arow, chunk));
            }
            uint32_t bhr[4][4], blr[4][4];
            #pragma unroll
            for (int nb = 0; nb < 4; nb++) {
                int brow = warp_n * 64 + nb * 16 + (lane & 15);
                ldsm4(bhr[nb], stg + 16384 + swz(brow, chunk));
                ldsm4(blr[nb], stg + 24576 + swz(brow, chunk));
            }
            #pragma unroll
            for (int mf = 0; mf < 2; mf++)
                #pragma unroll
                for (int nf = 0; nf < 8; nf++) {
                    int nb = nf >> 1, h = nf & 1;
                    float* d = acc[mf][nf];
                    mma_bf16(d, ah[mf], bhr[nb][h], bhr[nb][h + 2]);
                    mma_bf16(d, ah[mf], blr[nb][h], blr[nb][h + 2]);
                    mma_bf16(d, al[mf], bhr[nb][h], bhr[nb][h + 2]);
                }
        }
        __syncthreads();
    }

    // ---- epilogue: store C (+ optional split emit, + attention-dot partials) ----
    const int slot = (blockIdx.x * 2 + warp_n) * NN;
    #pragma unroll
    for (int mf = 0; mf < 2; mf++) {
        int r0 = rowBase + warp_m * 32 + mf * 16 + (lane >> 2);
        float s0 = 0.f, s1 = 0.f, d0 = 0.f, d1 = 0.f;
        #pragma unroll
        for (int nf = 0; nf < 8; nf++) {
            int col = colBase + warp_n * 64 + nf * 8 + (lane & 3) * 2;
            #pragma unroll
            for (int half = 0; half < 2; half++) {
                int r = r0 + half * 8;
                if (r < NN) {
                    float v0 = acc[mf][nf][2 * half], v1 = acc[mf][nf][2 * half + 1];
                    *(float2*)(out + (size_t)r * DD + col) = make_float2(v0, v1);
                    if (ehi) {
                        __nv_bfloat16 h0 = __float2bfloat16(v0);
                        __nv_bfloat16 h1 = __float2bfloat16(v1);
                        *(__nv_bfloat162*)(ehi + (size_t)r * DD + col) = __halves2bfloat162(h0, h1);
                        *(__nv_bfloat162*)(elo + (size_t)r * DD + col) = __halves2bfloat162(
                            __float2bfloat16(v0 - __bfloat162float(h0)),
                            __float2bfloat16(v1 - __bfloat162float(h1)));
                    }
                }
            }
            if (dots) {
                float as0 = asrc[col], as1 = asrc[col + 1];
                float ad0 = adst[col], ad1 = adst[col + 1];
                s0 = fmaf(acc[mf][nf][0], as0, fmaf(acc[mf][nf][1], as1, s0));
                d0 = fmaf(acc[mf][nf][0], ad0, fmaf(acc[mf][nf][1], ad1, d0));
                s1 = fmaf(acc[mf][nf][2], as0, fmaf(acc[mf][nf][3], as1, s1));
                d1 = fmaf(acc[mf][nf][2], ad0, fmaf(acc[mf][nf][3], ad1, d1));
            }
        }
        if (dots) {
            #pragma unroll
            for (int o = 1; o <= 2; o <<= 1) {
                s0 += __shfl_xor_sync(0xFFFFFFFFu, s0, o);
                s1 += __shfl_xor_sync(0xFFFFFFFFu, s1, o);
                d0 += __shfl_xor_sync(0xFFFFFFFFu, d0, o);
                d1 += __shfl_xor_sync(0xFFFFFFFFu, d1, o);
            }
            if ((lane & 3) == 0) {
                if (r0 < NN)     { g_esp[slot + r0] = s0;     g_edp[slot + r0] = d0; }
                if (r0 + 8 < NN) { g_esp[slot + r0 + 8] = s1; g_edp[slot + r0 + 8] = d1; }
            }
        }
    }
}

// ---------------- collapse 4 dot partials into totals ----------------
__global__ void k_sumdots() {
    int i = blockIdx.x * blockDim.x + threadIdx.x;
    if (i >= NN) return;
    g_est[i] = g_esp[i] + g_esp[NN + i] + g_esp[2 * NN + i] + g_esp[3 * NN + i];
    g_edt[i] = g_edp[i] + g_edp[NN + i] + g_edp[2 * NN + i] + g_edp[3 * NN + i];
}

// ---------------- fused GAT aggregate ----------------
#define MAXE 64
__global__ void __launch_bounds__(256)
k_gat(const float* __restrict__ bias, int dorelu) {
    __shared__ float sv[8][MAXE];
    __shared__ int   ss[8][MAXE];
    int wid = threadIdx.x >> 5, lane = threadIdx.x & 31;
    int n = blockIdx.x * 8 + wid;
    if (n >= NN) return;
    int start = g_rowptr[n], end = g_rowptr[n + 1];
    int deg = end - start;
    float ed = g_edt[n];

    float acc[8] = {};
    float sum = 0.f;
    float m = -3.4e38f;

    if (deg <= MAXE) {
        // pass 1: compute v, cache v+src in smem, warp max
        for (int j0 = 0; j0 < deg; j0 += 32) {
            int j = j0 + lane;
            float v = -3.4e38f;
            if (j < deg) {
                int s = g_csrc[start + j];
                v = g_est[s] + ed;
                v = v > 0.f ? v : 0.2f * v;
                sv[wid][j] = v;
                ss[wid][j] = s;
            }
            m = fmaxf(m, v);
        }
        #pragma unroll
        for (int o = 16; o > 0; o >>= 1) m = fmaxf(m, __shfl_xor_sync(0xFFFFFFFFu, m, o));
        __syncwarp();
        // pass 2: smem broadcast, zero attention reloads
        for (int j = 0; j < deg; j++) {
            float ee = __expf(sv[wid][j] - m);
            sum += ee;
            const float4* row = (const float4*)(g_hw + (size_t)ss[wid][j] * DD);
            float4 a = row[lane], b = row[lane + 32];
            acc[0] = fmaf(ee, a.x, acc[0]); acc[1] = fmaf(ee, a.y, acc[1]);
            acc[2] = fmaf(ee, a.z, acc[2]); acc[3] = fmaf(ee, a.w, acc[3]);
            acc[4] = fmaf(ee, b.x, acc[4]); acc[5] = fmaf(ee, b.y, acc[5]);
            acc[6] = fmaf(ee, b.z, acc[6]); acc[7] = fmaf(ee, b.w, acc[7]);
        }
    } else {
        // fallback (deg > MAXE): recompute path
        for (int j = start + lane; j < end; j += 32) {
            float v = g_est[g_csrc[j]] + ed;
            v = v > 0.f ? v : 0.2f * v;
            m = fmaxf(m, v);
        }
        #pragma unroll
        for (int o = 16; o > 0; o >>= 1) m = fmaxf(m, __shfl_xor_sync(0xFFFFFFFFu, m, o));
        for (int j = start; j < end; j++) {
            int s = g_csrc[j];
            float v = g_est[s] + ed;
            v = v > 0.f ? v : 0.2f * v;
            float ee = __expf(v - m);
            sum += ee;
            const float4* row = (const float4*)(g_hw + (size_t)s * DD);
            float4 a = row[lane], b = row[lane + 32];
            acc[0] = fmaf(ee, a.x, acc[0]); acc[1] = fmaf(ee, a.y, acc[1]);
            acc[2] = fmaf(ee, a.z, acc[2]); acc[3] = fmaf(ee, a.w, acc[3]);
            acc[4] = fmaf(ee, b.x, acc[4]); acc[5] = fmaf(ee, b.y, acc[5]);
            acc[6] = fmaf(ee, b.z, acc[6]); acc[7] = fmaf(ee, b.w, acc[7]);
        }
    }
    float inv = (deg > 0) ? 1.0f / sum : 0.f;

    float4 b0 = ((const float4*)bias)[lane];
    float4 b1 = ((const float4*)bias)[lane + 32];
    float o[8] = {acc[0] * inv + b0.x, acc[1] * inv + b0.y,
                  acc[2] * inv + b0.z, acc[3] * inv + b0.w,
                  acc[4] * inv + b1.x, acc[5] * inv + b1.y,
                  acc[6] * inv + b1.z, acc[7] * inv + b1.w};
    if (dorelu) {
        #pragma unroll
        for (int j = 0; j < 8; j++) o[j] = fmaxf(o[j], 0.f);
    }
    __nv_bfloat162 hp[4], lp[4];
    #pragma unroll
    for (int j = 0; j < 4; j++) {
        __nv_bfloat16 h0 = __float2bfloat16(o[2 * j]);
        __nv_bfloat16 h1 = __float2bfloat16(o[2 * j + 1]);
        hp[j] = __halves2bfloat162(h0, h1);
        lp[j] = __halves2bfloat162(__float2bfloat16(o[2 * j] - __bfloat162float(h0)),
                                   __float2bfloat16(o[2 * j + 1] - __bfloat162float(h1)));
    }
    __nv_bfloat16* dh = g_ahi + (size_t)n * DD;
    __nv_bfloat16* dl = g_alo + (size_t)n * DD;
    *(uint2*)(dh + 4 * lane)       = make_uint2(((uint2*)hp)[0].x, ((uint2*)hp)[0].y);
    *(uint2*)(dh + 128 + 4 * lane) = make_uint2(((uint2*)hp)[1].x, ((uint2*)hp)[1].y);
    *(uint2*)(dl + 4 * lane)       = make_uint2(((uint2*)lp)[0].x, ((uint2*)lp)[0].y);
    *(uint2*)(dl + 128 + 4 * lane) = make_uint2(((uint2*)lp)[1].x, ((uint2*)lp)[1].y);
}

// ---------------- launch ----------------
extern "C" void kernel_launch(void* const* d_in, const int* in_sizes, int n_in,
                              void* d_out, int out_size) {
    const float* x     = (const float*)d_in[0];
    const void*  ei    = d_in[1];
    const float* W1    = (const float*)d_in[2];
    const float* W2    = (const float*)d_in[3];
    const float* Ws    = (const float*)d_in[4];
    const float* a_src = (const float*)d_in[5];
    const float* a_dst = (const float*)d_in[6];
    const float* bias  = (const float*)d_in[7];
    const float* W3    = (const float*)d_in[8];
    float* out = (float*)d_out;

    float* p_hw;
    int* p_deg;
    __nv_bfloat16 *p_ahi, *p_alo, *p_a2hi, *p_a2lo, *p_bhi, *p_blo;
    cudaGetSymbolAddress((void**)&p_hw,   g_hw);
    cudaGetSymbolAddress((void**)&p_deg,  g_deg);
    cudaGetSymbolAddress((void**)&p_ahi,  g_ahi);
    cudaGetSymbolAddress((void**)&p_alo,  g_alo);
    cudaGetSymbolAddress((void**)&p_a2hi, g_a2hi);
    cudaGetSymbolAddress((void**)&p_a2lo, g_a2lo);
    cudaGetSymbolAddress((void**)&p_bhi,  g_bhi);
    cudaGetSymbolAddress((void**)&p_blo,  g_blo);

    cudaFuncSetAttribute(k_gemm_mma, cudaFuncAttributeMaxDynamicSharedMemorySize, SMEM_BYTES);

    // one-time: indices, CSR, x split, all weight splits
    k_detect<<<1, 128>>>((const int*)ei);
    cudaMemsetAsync(p_deg, 0, NN * sizeof(int));
    k_convert<<<256, 256>>>(ei);
    k_scan<<<1, 1024>>>();
    k_fill<<<256, 256>>>();
    k_convA<<<(NN * DD / 8 + 255) / 256, 256>>>(x);
    k_prepAllB<<<(9 * DD * DD + 255) / 256, 256>>>(W1, W2, Ws, W3);

    dim3 gg(2, (NN + 127) / 128);
    const int BW = DD * DD;

    // hw = x@W1 (emit split to S1); h = hw@W2 (emit split to S0)
    k_gemm_mma<<<gg, GT, SMEM_BYTES>>>(p_hw, p_ahi, p_alo, p_bhi, p_blo,
                                       p_a2hi, p_a2lo, nullptr, nullptr, 0);
    k_gemm_mma<<<gg, GT, SMEM_BYTES>>>(p_hw, p_a2hi, p_a2lo, p_bhi + BW, p_blo + BW,
                                       p_ahi, p_alo, nullptr, nullptr, 0);

    for (int l = 0; l < 6; l++) {
        k_gemm_mma<<<gg, GT, SMEM_BYTES>>>(p_hw, p_ahi, p_alo,
                                           p_bhi + (size_t)(2 + l) * BW, p_blo + (size_t)(2 + l) * BW,
                                           nullptr, nullptr, a_src + l * DD, a_dst + l * DD, 1);
        k_sumdots<<<(NN + 255) / 256, 256>>>();
        k_gat<<<(NN + 7) / 8, 256>>>(bias + l * DD, l == 5 ? 1 : 0);
    }

    // out = relu(h) @ (W3_top + W3_bot)   (relu folded into last k_gat's split)
    k_gemm_mma<<<gg, GT, SMEM_BYTES>>>(out, p_ahi, p_alo, p_bhi + 8 * BW, p_blo + 8 * BW,
                                       nullptr, nullptr, nullptr, nullptr, 0);
}

// round 10
// speedup vs baseline: 2.8347x; 1.1127x over previous
#include <cuda_runtime.h>
#include <cuda_bf16.h>
#include <cstdint>

#define NN   20000
#define EE   320000
#define DD   256

// ---------------- scratch (static device globals; no allocs allowed) ----------------
__device__ __align__(16) float g_hw[(size_t)NN * DD];
__device__ __align__(16) __nv_bfloat16 g_ahi [(size_t)NN * DD];   // split buffer S0
__device__ __align__(16) __nv_bfloat16 g_alo [(size_t)NN * DD];
__device__ __align__(16) __nv_bfloat16 g_a2hi[(size_t)NN * DD];   // split buffer S1
__device__ __align__(16) __nv_bfloat16 g_a2lo[(size_t)NN * DD];
__device__ __align__(16) __nv_bfloat16 g_bhi[9 * DD * DD];        // 9 weight slots, B^T split
__device__ __align__(16) __nv_bfloat16 g_blo[9 * DD * DD];
__device__ float g_dt[2 * NN];    // [0,NN): e_src totals, [NN,2NN): e_dst totals
__device__ int g_srcA[EE], g_dstA[EE], g_csrc[EE];
__device__ __align__(16) int g_deg[NN];
__device__ int g_rowptr[NN + 1], g_cursor[NN];
__device__ int g_is64;

// ---------------- helpers ----------------
__device__ __forceinline__ uint32_t smem_u32(const void* p) {
    uint32_t a;
    asm("{ .reg .u64 t; cvta.to.shared.u64 t, %1; cvt.u32.u64 %0, t; }" : "=r"(a) : "l"(p));
    return a;
}

// ---------------- parallel dtype detect ----------------
__global__ void k_detect(const int* ei32) {
    __shared__ int anynz;
    int t = threadIdx.x;                     // 128 threads
    if (t == 0) anynz = 0;
    __syncthreads();
    int nz = (ei32[2 * t + 1] != 0);
    if (__any_sync(0xFFFFFFFFu, nz) && (t & 31) == 0) atomicOr(&anynz, 1);
    __syncthreads();
    if (t == 0) g_is64 = anynz ? 0 : 1;      // all high words zero => int64
}

// ---------------- convert + degree count (one edge per thread) ----------------
__global__ void k_convert(const void* ei) {
    int i = blockIdx.x * blockDim.x + threadIdx.x;
    if (i >= EE) return;
    int s, t;
    if (g_is64) {
        const long long* p = (const long long*)ei;
        s = (int)p[i]; t = (int)p[EE + i];
    } else {
        const int* p = (const int*)ei;
        s = p[i]; t = p[EE + i];
    }
    g_srcA[i] = s; g_dstA[i] = t;
    atomicAdd(&g_deg[t], 1);
}

// ---------------- single-block warp-shuffle scan (NN = 1000 * 20) ----------------
__global__ void k_scan() {
    __shared__ int wsum[32];
    int t = threadIdx.x, lane = t & 31, w = t >> 5;
    int loc[20];
    int s = 0;
    if (t < 1000) {
        const int4* p = (const int4*)(g_deg + t * 20);
        #pragma unroll
        for (int i = 0; i < 5; i++) {
            int4 v = p[i];
            loc[4 * i]     = s; s += v.x;
            loc[4 * i + 1] = s; s += v.y;
            loc[4 * i + 2] = s; s += v.z;
            loc[4 * i + 3] = s; s += v.w;
        }
    }
    int inc = s;
    #pragma unroll
    for (int o = 1; o < 32; o <<= 1) {
        int v = __shfl_up_sync(0xFFFFFFFFu, inc, o);
        if (lane >= o) inc += v;
    }
    if (lane == 31) wsum[w] = inc;
    __syncthreads();
    if (w == 0) {
        int v = wsum[lane];
        int wi = v;
        #pragma unroll
        for (int o = 1; o < 32; o <<= 1) {
            int u = __shfl_up_sync(0xFFFFFFFFu, wi, o);
            if (lane >= o) wi += u;
        }
        wsum[lane] = wi - v;   // exclusive
    }
    __syncthreads();
    int excl = wsum[w] + (inc - s);
    if (t < 1000) {
        int base = t * 20;
        #pragma unroll
        for (int i = 0; i < 20; i++) {
            int r = excl + loc[i];
            g_rowptr[base + i] = r;
            g_cursor[base + i] = r;
        }
    }
    if (t == 0) g_rowptr[NN] = EE;
}

__global__ void k_fill() {
    int i = blockIdx.x * blockDim.x + threadIdx.x;
    if (i >= EE) return;
    int pos = atomicAdd(&g_cursor[g_dstA[i]], 1);
    g_csrc[pos] = g_srcA[i];
}

// ---------------- fp32 -> bf16 hi/lo split of x ----------------
__global__ void k_convA(const float* __restrict__ src) {
    int i = blockIdx.x * blockDim.x + threadIdx.x;
    const int total = NN * DD / 8;
    if (i >= total) return;
    float4 v0 = ((const float4*)src)[2 * i];
    float4 v1 = ((const float4*)src)[2 * i + 1];
    float f[8] = {v0.x, v0.y, v0.z, v0.w, v1.x, v1.y, v1.z, v1.w};
    __nv_bfloat162 hp[4], lp[4];
    #pragma unroll
    for (int j = 0; j < 4; j++) {
        __nv_bfloat16 h0 = __float2bfloat16(f[2 * j]);
        __nv_bfloat16 h1 = __float2bfloat16(f[2 * j + 1]);
        hp[j] = __halves2bfloat162(h0, h1);
        lp[j] = __halves2bfloat162(__float2bfloat16(f[2 * j] - __bfloat162float(h0)),
                                   __float2bfloat16(f[2 * j + 1] - __bfloat162float(h1)));
    }
    *(uint4*)(g_ahi + 8 * (size_t)i) = *(uint4*)hp;
    *(uint4*)(g_alo + 8 * (size_t)i) = *(uint4*)lp;
}

// ---------------- all 9 weights -> B^T bf16 hi/lo split (slot 8 folds W3) ----------------
__global__ void k_prepAllB(const float* __restrict__ W1, const float* __restrict__ W2,
                           const float* __restrict__ Ws, const float* __restrict__ W3) {
    int i = blockIdx.x * blockDim.x + threadIdx.x;
    if (i >= 9 * DD * DD) return;
    int slot = i >> 16, idx = i & 65535;
    int n = idx >> 8, k = idx & 255;
    float v;
    if (slot == 0)      v = W1[k * DD + n];
    else if (slot == 1) v = W2[k * DD + n];
    else if (slot < 8)  v = Ws[(size_t)(slot - 2) * DD * DD + k * DD + n];
    else                v = W3[k * DD + n] + W3[(k + DD) * DD + n];
    __nv_bfloat16 h = __float2bfloat16(v);
    g_bhi[i] = h;
    g_blo[i] = __float2bfloat16(v - __bfloat162float(h));
}

// ---------------- mma.sync bf16 GEMM: out[M,256] = A @ B ----------------
#define GT 256
#define STAGE_BYTES 32768
#define SMEM_BYTES  (2 * STAGE_BYTES)

__device__ __forceinline__ uint32_t swz(int row, int chunk) {
    return (uint32_t)(row * 64 + ((chunk ^ ((row >> 1) & 3)) << 4));
}
__device__ __forceinline__ void cpa16(uint32_t dst, const void* src, int sz) {
    asm volatile("cp.async.cg.shared.global [%0], [%1], 16, %2;"
                 :: "r"(dst), "l"(src), "r"(sz) : "memory");
}
__device__ __forceinline__ void ldsm4(uint32_t* r, uint32_t addr) {
    asm volatile("ldmatrix.sync.aligned.m8n8.x4.shared.b16 {%0,%1,%2,%3}, [%4];"
                 : "=r"(r[0]), "=r"(r[1]), "=r"(r[2]), "=r"(r[3]) : "r"(addr));
}
__device__ __forceinline__ void mma_bf16(float* d, const uint32_t* a, uint32_t b0, uint32_t b1) {
    asm volatile("mma.sync.aligned.m16n8k16.row.col.f32.bf16.bf16.f32 "
                 "{%0,%1,%2,%3}, {%4,%5,%6,%7}, {%8,%9}, {%0,%1,%2,%3};"
                 : "+f"(d[0]), "+f"(d[1]), "+f"(d[2]), "+f"(d[3])
                 : "r"(a[0]), "r"(a[1]), "r"(a[2]), "r"(a[3]), "r"(b0), "r"(b1));
}

__device__ __forceinline__ void load_stage(uint32_t sb, int stage, int kk,
                                           int rowBase, int colBase, int tid,
                                           const __nv_bfloat16* ahi, const __nv_bfloat16* alo,
                                           const __nv_bfloat16* bhi, const __nv_bfloat16* blo) {
    uint32_t base = sb + stage * STAGE_BYTES;
    #pragma unroll
    for (int i = 0; i < 8; i++) {
        int id = i * GT + tid;
        int mat = id >> 9;
        int rem = id & 511;
        int row = rem >> 2, chunk = rem & 3;
        uint32_t dst = base + mat * 8192 + swz(row, chunk);
        const __nv_bfloat16* sbase =
            (mat == 0) ? ahi : (mat == 1) ? alo : (mat == 2) ? bhi : blo;
        int grow = (mat < 2) ? (rowBase + row) : (colBase + row);
        int ok = (mat >= 2) || (grow < NN);
        int gcl = ok ? grow : 0;
        cpa16(dst, sbase + (size_t)gcl * DD + kk * 32 + chunk * 8, ok ? 16 : 0);
    }
}

__global__ void __launch_bounds__(GT, 2)
k_gemm_mma(float* __restrict__ out,
           const __nv_bfloat16* __restrict__ ahi, const __nv_bfloat16* __restrict__ alo,
           const __nv_bfloat16* __restrict__ bhi, const __nv_bfloat16* __restrict__ blo,
           __nv_bfloat16* __restrict__ ehi, __nv_bfloat16* __restrict__ elo,
           const float* __restrict__ asrc, const float* __restrict__ adst, int dots) {
    extern __shared__ char sm[];
    uint32_t sb = smem_u32(sm);
    const int tid = threadIdx.x, lane = tid & 31, wid = tid >> 5;
    const int warp_m = wid & 3;
    const int warp_n = wid >> 2;
    const int colBase = blockIdx.x * 128;
    const int rowBase = blockIdx.y * 128;

    float acc[2][8][4] = {};

    load_stage(sb, 0, 0, rowBase, colBase, tid, ahi, alo, bhi, blo);
    asm volatile("cp.async.commit_group;" ::: "memory");

    for (int s = 0; s < 8; s++) {
        if (s + 1 < 8) load_stage(sb, (s + 1) & 1, s + 1, rowBase, colBase, tid, ahi, alo, bhi, blo);
        asm volatile("cp.async.commit_group;" ::: "memory");
        asm volatile("cp.async.wait_group 1;" ::: "memory");
        __syncthreads();

        uint32_t stg = sb + (s & 1) * STAGE_BYTES;
        #pragma unroll
        for (int k16 = 0; k16 < 2; k16++) {
            int chunk = k16 * 2 + (lane >> 4);
            uint32_t ah[2][4], al[2][4];
            #pragma unroll
            for (int mf = 0; mf < 2; mf++) {
                int arow = warp_m * 32 + mf * 16 + (lane & 15);
                ldsm4(ah[mf], stg + 0    + swz(arow, chunk));
                ldsm4(al[mf], stg + 8192 + swz(arow, chunk));
            }
            // B fragments in 2 groups of 2 nb -> live B regs 16 instead of 32
            #pragma unroll
            for (int grp = 0; grp < 2; grp++) {
                uint32_t bhr[2][4], blr[2][4];
                #pragma unroll
                for (int nb2 = 0; nb2 < 2; nb2++) {
                    int brow = warp_n * 64 + (grp * 2 + nb2) * 16 + (lane & 15);
                    ldsm4(bhr[nb2], stg + 16384 + swz(brow, chunk));
                    ldsm4(blr[nb2], stg + 24576 + swz(brow, chunk));
                }
                #pragma unroll
                for (int mf = 0; mf < 2; mf++)
                    #pragma unroll
                    for (int nf2 = 0; nf2 < 4; nf2++) {
                        int nb2 = nf2 >> 1, h = nf2 & 1;
                        float* d = acc[mf][grp * 4 + nf2];
                        mma_bf16(d, ah[mf], bhr[nb2][h], bhr[nb2][h + 2]);
                        mma_bf16(d, ah[mf], blr[nb2][h], blr[nb2][h + 2]);
                        mma_bf16(d, al[mf], bhr[nb2][h], bhr[nb2][h + 2]);
                    }
            }
        }
        __syncthreads();
    }

    // ---- epilogue: store C (+ optional split emit, + attention-dot atomics) ----
    #pragma unroll
    for (int mf = 0; mf < 2; mf++) {
        int r0 = rowBase + warp_m * 32 + mf * 16 + (lane >> 2);
        float s0 = 0.f, s1 = 0.f, d0 = 0.f, d1 = 0.f;
        #pragma unroll
        for (int nf = 0; nf < 8; nf++) {
            int col = colBase + warp_n * 64 + nf * 8 + (lane & 3) * 2;
            #pragma unroll
            for (int half = 0; half < 2; half++) {
                int r = r0 + half * 8;
                if (r < NN) {
                    float v0 = acc[mf][nf][2 * half], v1 = acc[mf][nf][2 * half + 1];
                    *(float2*)(out + (size_t)r * DD + col) = make_float2(v0, v1);
                    if (ehi) {
                        __nv_bfloat16 h0 = __float2bfloat16(v0);
                        __nv_bfloat16 h1 = __float2bfloat16(v1);
                        *(__nv_bfloat162*)(ehi + (size_t)r * DD + col) = __halves2bfloat162(h0, h1);
                        *(__nv_bfloat162*)(elo + (size_t)r * DD + col) = __halves2bfloat162(
                            __float2bfloat16(v0 - __bfloat162float(h0)),
                            __float2bfloat16(v1 - __bfloat162float(h1)));
                    }
                }
            }
            if (dots) {
                float as0 = asrc[col], as1 = asrc[col + 1];
                float ad0 = adst[col], ad1 = adst[col + 1];
                s0 = fmaf(acc[mf][nf][0], as0, fmaf(acc[mf][nf][1], as1, s0));
                d0 = fmaf(acc[mf][nf][0], ad0, fmaf(acc[mf][nf][1], ad1, d0));
                s1 = fmaf(acc[mf][nf][2], as0, fmaf(acc[mf][nf][3], as1, s1));
                d1 = fmaf(acc[mf][nf][2], ad0, fmaf(acc[mf][nf][3], ad1, d1));
            }
        }
        if (dots) {
            #pragma unroll
            for (int o = 1; o <= 2; o <<= 1) {
                s0 += __shfl_xor_sync(0xFFFFFFFFu, s0, o);
                s1 += __shfl_xor_sync(0xFFFFFFFFu, s1, o);
                d0 += __shfl_xor_sync(0xFFFFFFFFu, d0, o);
                d1 += __shfl_xor_sync(0xFFFFFFFFu, d1, o);
            }
            if ((lane & 3) == 0) {
                if (r0 < NN)     { atomicAdd(&g_dt[r0], s0);     atomicAdd(&g_dt[NN + r0], d0); }
                if (r0 + 8 < NN) { atomicAdd(&g_dt[r0 + 8], s1); atomicAdd(&g_dt[NN + r0 + 8], d1); }
            }
        }
    }
}

// ---------------- fused GAT aggregate ----------------
#define MAXE 64
__global__ void __launch_bounds__(256)
k_gat(const float* __restrict__ bias, int dorelu) {
    __shared__ float sv[8][MAXE];
    __shared__ int   ss[8][MAXE];
    int wid = threadIdx.x >> 5, lane = threadIdx.x & 31;
    int n = blockIdx.x * 8 + wid;
    if (n >= NN) return;
    int start = g_rowptr[n], end = g_rowptr[n + 1];
    int deg = end - start;
    float ed = g_dt[NN + n];

    float acc[8] = {};
    float sum = 0.f;
    float m = -3.4e38f;

    if (deg <= MAXE) {
        for (int j0 = 0; j0 < deg; j0 += 32) {
            int j = j0 + lane;
            float v = -3.4e38f;
            if (j < deg) {
                int s = g_csrc[start + j];
                v = g_dt[s] + ed;
                v = v > 0.f ? v : 0.2f * v;
                sv[wid][j] = v;
                ss[wid][j] = s;
            }
            m = fmaxf(m, v);
        }
        #pragma unroll
        for (int o = 16; o > 0; o >>= 1) m = fmaxf(m, __shfl_xor_sync(0xFFFFFFFFu, m, o));
        __syncwarp();
        for (int j = 0; j < deg; j++) {
            float ee = __expf(sv[wid][j] - m);
            sum += ee;
            const float4* row = (const float4*)(g_hw + (size_t)ss[wid][j] * DD);
            float4 a = row[lane], b = row[lane + 32];
            acc[0] = fmaf(ee, a.x, acc[0]); acc[1] = fmaf(ee, a.y, acc[1]);
            acc[2] = fmaf(ee, a.z, acc[2]); acc[3] = fmaf(ee, a.w, acc[3]);
            acc[4] = fmaf(ee, b.x, acc[4]); acc[5] = fmaf(ee, b.y, acc[5]);
            acc[6] = fmaf(ee, b.z, acc[6]); acc[7] = fmaf(ee, b.w, acc[7]);
        }
    } else {
        for (int j = start + lane; j < end; j += 32) {
            float v = g_dt[g_csrc[j]] + ed;
            v = v > 0.f ? v : 0.2f * v;
            m = fmaxf(m, v);
        }
        #pragma unroll
        for (int o = 16; o > 0; o >>= 1) m = fmaxf(m, __shfl_xor_sync(0xFFFFFFFFu, m, o));
        for (int j = start; j < end; j++) {
            int s = g_csrc[j];
            float v = g_dt[s] + ed;
            v = v > 0.f ? v : 0.2f * v;
            float ee = __expf(v - m);
            sum += ee;
            const float4* row = (const float4*)(g_hw + (size_t)s * DD);
            float4 a = row[lane], b = row[lane + 32];
            acc[0] = fmaf(ee, a.x, acc[0]); acc[1] = fmaf(ee, a.y, acc[1]);
            acc[2] = fmaf(ee, a.z, acc[2]); acc[3] = fmaf(ee, a.w, acc[3]);
            acc[4] = fmaf(ee, b.x, acc[4]); acc[5] = fmaf(ee, b.y, acc[5]);
            acc[6] = fmaf(ee, b.z, acc[6]); acc[7] = fmaf(ee, b.w, acc[7]);
        }
    }
    float inv = (deg > 0) ? 1.0f / sum : 0.f;

    float4 b0 = ((const float4*)bias)[lane];
    float4 b1 = ((const float4*)bias)[lane + 32];
    float o[8] = {acc[0] * inv + b0.x, acc[1] * inv + b0.y,
                  acc[2] * inv + b0.z, acc[3] * inv + b0.w,
                  acc[4] * inv + b1.x, acc[5] * inv + b1.y,
                  acc[6] * inv + b1.z, acc[7] * inv + b1.w};
    if (dorelu) {
        #pragma unroll
        for (int j = 0; j < 8; j++) o[j] = fmaxf(o[j], 0.f);
    }
    __nv_bfloat162 hp[4], lp[4];
    #pragma unroll
    for (int j = 0; j < 4; j++) {
        __nv_bfloat16 h0 = __float2bfloat16(o[2 * j]);
        __nv_bfloat16 h1 = __float2bfloat16(o[2 * j + 1]);
        hp[j] = __halves2bfloat162(h0, h1);
        lp[j] = __halves2bfloat162(__float2bfloat16(o[2 * j] - __bfloat162float(h0)),
                                   __float2bfloat16(o[2 * j + 1] - __bfloat162float(h1)));
    }
    __nv_bfloat16* dh = g_ahi + (size_t)n * DD;
    __nv_bfloat16* dl = g_alo + (size_t)n * DD;
    *(uint2*)(dh + 4 * lane)       = make_uint2(((uint2*)hp)[0].x, ((uint2*)hp)[0].y);
    *(uint2*)(dh + 128 + 4 * lane) = make_uint2(((uint2*)hp)[1].x, ((uint2*)hp)[1].y);
    *(uint2*)(dl + 4 * lane)       = make_uint2(((uint2*)lp)[0].x, ((uint2*)lp)[0].y);
    *(uint2*)(dl + 128 + 4 * lane) = make_uint2(((uint2*)lp)[1].x, ((uint2*)lp)[1].y);
}

// ---------------- launch ----------------
extern "C" void kernel_launch(void* const* d_in, const int* in_sizes, int n_in,
                              void* d_out, int out_size) {
    const float* x     = (const float*)d_in[0];
    const void*  ei    = d_in[1];
    const float* W1    = (const float*)d_in[2];
    const float* W2    = (const float*)d_in[3];
    const float* Ws    = (const float*)d_in[4];
    const float* a_src = (const float*)d_in[5];
    const float* a_dst = (const float*)d_in[6];
    const float* bias  = (const float*)d_in[7];
    const float* W3    = (const float*)d_in[8];
    float* out = (float*)d_out;

    float *p_hw, *p_dt;
    int* p_deg;
    __nv_bfloat16 *p_ahi, *p_alo, *p_a2hi, *p_a2lo, *p_bhi, *p_blo;
    cudaGetSymbolAddress((void**)&p_hw,   g_hw);
    cudaGetSymbolAddress((void**)&p_dt,   g_dt);
    cudaGetSymbolAddress((void**)&p_deg,  g_deg);
    cudaGetSymbolAddress((void**)&p_ahi,  g_ahi);
    cudaGetSymbolAddress((void**)&p_alo,  g_alo);
    cudaGetSymbolAddress((void**)&p_a2hi, g_a2hi);
    cudaGetSymbolAddress((void**)&p_a2lo, g_a2lo);
    cudaGetSymbolAddress((void**)&p_bhi,  g_bhi);
    cudaGetSymbolAddress((void**)&p_blo,  g_blo);

    cudaFuncSetAttribute(k_gemm_mma, cudaFuncAttributeMaxDynamicSharedMemorySize, SMEM_BYTES);

    // one-time: indices, CSR, x split, all weight splits
    k_detect<<<1, 128>>>((const int*)ei);
    cudaMemsetAsync(p_deg, 0, NN * sizeof(int));
    k_convert<<<(EE + 255) / 256, 256>>>(ei);
    k_scan<<<1, 1024>>>();
    k_fill<<<(EE + 255) / 256, 256>>>();
    k_convA<<<(NN * DD / 8 + 255) / 256, 256>>>(x);
    k_prepAllB<<<(9 * DD * DD + 255) / 256, 256>>>(W1, W2, Ws, W3);

    dim3 gg(2, (NN + 127) / 128);
    const int BW = DD * DD;

    // hw = x@W1 (emit split to S1); h = hw@W2 (emit split to S0)
    k_gemm_mma<<<gg, GT, SMEM_BYTES>>>(p_hw, p_ahi, p_alo, p_bhi, p_blo,
                                       p_a2hi, p_a2lo, nullptr, nullptr, 0);
    k_gemm_mma<<<gg, GT, SMEM_BYTES>>>(p_hw, p_a2hi, p_a2lo, p_bhi + BW, p_blo + BW,
                                       p_ahi, p_alo, nullptr, nullptr, 0);

    for (int l = 0; l < 6; l++) {
        cudaMemsetAsync(p_dt, 0, 2 * NN * sizeof(float));
        k_gemm_mma<<<gg, GT, SMEM_BYTES>>>(p_hw, p_ahi, p_alo,
                                           p_bhi + (size_t)(2 + l) * BW, p_blo + (size_t)(2 + l) * BW,
                                           nullptr, nullptr, a_src + l * DD, a_dst + l * DD, 1);
        k_gat<<<(NN + 7) / 8, 256>>>(bias + l * DD, l == 5 ? 1 : 0);
    }

    // out = relu(h) @ (W3_top + W3_bot)   (relu folded into last k_gat's split)
    k_gemm_mma<<<gg, GT, SMEM_BYTES>>>(out, p_ahi, p_alo, p_bhi + 8 * BW, p_blo + 8 * BW,
                                       nullptr, nullptr, nullptr, nullptr, 0);
}

// round 11
// speedup vs baseline: 2.9908x; 1.0550x over previous
#include <cuda_runtime.h>
#include <cuda_bf16.h>
#include <cstdint>

#define NN   20000
#define EE   320000
#define DD   256

// ---------------- scratch (static device globals; no allocs allowed) ----------------
__device__ __align__(16) float g_hw[(size_t)NN * DD];
__device__ __align__(16) __nv_bfloat16 g_ahi [(size_t)NN * DD];   // split buffer S0
__device__ __align__(16) __nv_bfloat16 g_alo [(size_t)NN * DD];
__device__ __align__(16) __nv_bfloat16 g_a2hi[(size_t)NN * DD];   // split buffer S1
__device__ __align__(16) __nv_bfloat16 g_a2lo[(size_t)NN * DD];
__device__ __align__(16) __nv_bfloat16 g_bhi[9 * DD * DD];        // 9 weight slots, B^T split
__device__ __align__(16) __nv_bfloat16 g_blo[9 * DD * DD];
__device__ float g_dt[2 * NN];    // [0,NN): e_src totals, [NN,2NN): e_dst totals
__device__ int g_srcA[EE], g_dstA[EE], g_csrc[EE];
__device__ __align__(16) int g_deg[NN];
__device__ int g_rowptr[NN + 1], g_cursor[NN];
__device__ int g_is64;

// ---------------- helpers ----------------
__device__ __forceinline__ uint32_t smem_u32(const void* p) {
    uint32_t a;
    asm("{ .reg .u64 t; cvta.to.shared.u64 t, %1; cvt.u32.u64 %0, t; }" : "=r"(a) : "l"(p));
    return a;
}

// ---------------- parallel dtype detect ----------------
__global__ void k_detect(const int* ei32) {
    __shared__ int anynz;
    int t = threadIdx.x;                     // 128 threads
    if (t == 0) anynz = 0;
    __syncthreads();
    int nz = (ei32[2 * t + 1] != 0);
    if (__any_sync(0xFFFFFFFFu, nz) && (t & 31) == 0) atomicOr(&anynz, 1);
    __syncthreads();
    if (t == 0) g_is64 = anynz ? 0 : 1;      // all high words zero => int64
}

// ---------------- convert + degree count (one edge per thread) ----------------
__global__ void k_convert(const void* ei) {
    int i = blockIdx.x * blockDim.x + threadIdx.x;
    if (i >= EE) return;
    int s, t;
    if (g_is64) {
        const long long* p = (const long long*)ei;
        s = (int)p[i]; t = (int)p[EE + i];
    } else {
        const int* p = (const int*)ei;
        s = p[i]; t = p[EE + i];
    }
    g_srcA[i] = s; g_dstA[i] = t;
    atomicAdd(&g_deg[t], 1);
}

// ---------------- single-block warp-shuffle scan (NN = 1000 * 20) ----------------
__global__ void k_scan() {
    __shared__ int wsum[32];
    int t = threadIdx.x, lane = t & 31, w = t >> 5;
    int loc[20];
    int s = 0;
    if (t < 1000) {
        const int4* p = (const int4*)(g_deg + t * 20);
        #pragma unroll
        for (int i = 0; i < 5; i++) {
            int4 v = p[i];
            loc[4 * i]     = s; s += v.x;
            loc[4 * i + 1] = s; s += v.y;
            loc[4 * i + 2] = s; s += v.z;
            loc[4 * i + 3] = s; s += v.w;
        }
    }
    int inc = s;
    #pragma unroll
    for (int o = 1; o < 32; o <<= 1) {
        int v = __shfl_up_sync(0xFFFFFFFFu, inc, o);
        if (lane >= o) inc += v;
    }
    if (lane == 31) wsum[w] = inc;
    __syncthreads();
    if (w == 0) {
        int v = wsum[lane];
        int wi = v;
        #pragma unroll
        for (int o = 1; o < 32; o <<= 1) {
            int u = __shfl_up_sync(0xFFFFFFFFu, wi, o);
            if (lane >= o) wi += u;
        }
        wsum[lane] = wi - v;   // exclusive
    }
    __syncthreads();
    int excl = wsum[w] + (inc - s);
    if (t < 1000) {
        int base = t * 20;
        #pragma unroll
        for (int i = 0; i < 20; i++) {
            int r = excl + loc[i];
            g_rowptr[base + i] = r;
            g_cursor[base + i] = r;
        }
    }
    if (t == 0) g_rowptr[NN] = EE;
}

__global__ void k_fill() {
    int i = blockIdx.x * blockDim.x + threadIdx.x;
    if (i >= EE) return;
    int pos = atomicAdd(&g_cursor[g_dstA[i]], 1);
    g_csrc[pos] = g_srcA[i];
}

// ---------------- fp32 -> bf16 hi/lo split of x ----------------
__global__ void k_convA(const float* __restrict__ src) {
    int i = blockIdx.x * blockDim.x + threadIdx.x;
    const int total = NN * DD / 8;
    if (i >= total) return;
    float4 v0 = ((const float4*)src)[2 * i];
    float4 v1 = ((const float4*)src)[2 * i + 1];
    float f[8] = {v0.x, v0.y, v0.z, v0.w, v1.x, v1.y, v1.z, v1.w};
    __nv_bfloat162 hp[4], lp[4];
    #pragma unroll
    for (int j = 0; j < 4; j++) {
        __nv_bfloat16 h0 = __float2bfloat16(f[2 * j]);
        __nv_bfloat16 h1 = __float2bfloat16(f[2 * j + 1]);
        hp[j] = __halves2bfloat162(h0, h1);
        lp[j] = __halves2bfloat162(__float2bfloat16(f[2 * j] - __bfloat162float(h0)),
                                   __float2bfloat16(f[2 * j + 1] - __bfloat162float(h1)));
    }
    *(uint4*)(g_ahi + 8 * (size_t)i) = *(uint4*)hp;
    *(uint4*)(g_alo + 8 * (size_t)i) = *(uint4*)lp;
}

// ---------------- all 9 weights -> B^T bf16 hi/lo split (slot 8 folds W3) ----------------
__global__ void k_prepAllB(const float* __restrict__ W1, const float* __restrict__ W2,
                           const float* __restrict__ Ws, const float* __restrict__ W3) {
    int i = blockIdx.x * blockDim.x + threadIdx.x;
    if (i >= 9 * DD * DD) return;
    int slot = i >> 16, idx = i & 65535;
    int n = idx >> 8, k = idx & 255;
    float v;
    if (slot == 0)      v = W1[k * DD + n];
    else if (slot == 1) v = W2[k * DD + n];
    else if (slot < 8)  v = Ws[(size_t)(slot - 2) * DD * DD + k * DD + n];
    else                v = W3[k * DD + n] + W3[(k + DD) * DD + n];
    __nv_bfloat16 h = __float2bfloat16(v);
    g_bhi[i] = h;
    g_blo[i] = __float2bfloat16(v - __bfloat162float(h));
}

// ---------------- mma.sync bf16 GEMM: out[M,256] = A @ B ----------------
// CTA tile 64 rows x 128 cols, BK=32, 256 threads (2 m-warps x 4 n-warps), occ 3.
// Stage: AH 4K | AL 4K | BH 8K | BL 8K = 24KB, 2 stages = 48KB.
#define GT 256
#define STAGE_BYTES 24576
#define SMEM_BYTES  (2 * STAGE_BYTES)
#define MTILE 64

__device__ __forceinline__ uint32_t swz(int row, int chunk) {
    return (uint32_t)(row * 64 + ((chunk ^ ((row >> 1) & 3)) << 4));
}
__device__ __forceinline__ void cpa16(uint32_t dst, const void* src, int sz) {
    asm volatile("cp.async.cg.shared.global [%0], [%1], 16, %2;"
                 :: "r"(dst), "l"(src), "r"(sz) : "memory");
}
__device__ __forceinline__ void ldsm4(uint32_t* r, uint32_t addr) {
    asm volatile("ldmatrix.sync.aligned.m8n8.x4.shared.b16 {%0,%1,%2,%3}, [%4];"
                 : "=r"(r[0]), "=r"(r[1]), "=r"(r[2]), "=r"(r[3]) : "r"(addr));
}
__device__ __forceinline__ void mma_bf16(float* d, const uint32_t* a, uint32_t b0, uint32_t b1) {
    asm volatile("mma.sync.aligned.m16n8k16.row.col.f32.bf16.bf16.f32 "
                 "{%0,%1,%2,%3}, {%4,%5,%6,%7}, {%8,%9}, {%0,%1,%2,%3};"
                 : "+f"(d[0]), "+f"(d[1]), "+f"(d[2]), "+f"(d[3])
                 : "r"(a[0]), "r"(a[1]), "r"(a[2]), "r"(a[3]), "r"(b0), "r"(b1));
}

__device__ __forceinline__ void load_stage(uint32_t sb, int stage, int kk,
                                           int rowBase, int colBase, int tid,
                                           const __nv_bfloat16* ahi, const __nv_bfloat16* alo,
                                           const __nv_bfloat16* bhi, const __nv_bfloat16* blo) {
    uint32_t base = sb + stage * STAGE_BYTES;
    // A: 2 mats x 64 rows x 4 chunks = 512 ops; B: 2 mats x 128 rows x 4 chunks = 1024 ops
    #pragma unroll
    for (int i = 0; i < 6; i++) {
        int id = i * GT + tid;           // 0..1535
        if (id < 512) {
            int mat = id >> 8, rem = id & 255;
            int row = rem >> 2, chunk = rem & 3;
            uint32_t dst = base + mat * 4096 + swz(row, chunk);
            const __nv_bfloat16* sbase = mat ? alo : ahi;
            int grow = rowBase + row;
            int ok = grow < NN;
            cpa16(dst, sbase + (size_t)(ok ? grow : 0) * DD + kk * 32 + chunk * 8, ok ? 16 : 0);
        } else {
            int idb = id - 512;
            int mat = idb >> 9, rem = idb & 511;
            int row = rem >> 2, chunk = rem & 3;
            uint32_t dst = base + 8192 + mat * 8192 + swz(row, chunk);
            const __nv_bfloat16* sbase = mat ? blo : bhi;
            cpa16(dst, sbase + (size_t)(colBase + row) * DD + kk * 32 + chunk * 8, 16);
        }
    }
}

__global__ void __launch_bounds__(GT, 3)
k_gemm_mma(float* __restrict__ out,
           const __nv_bfloat16* __restrict__ ahi, const __nv_bfloat16* __restrict__ alo,
           const __nv_bfloat16* __restrict__ bhi, const __nv_bfloat16* __restrict__ blo,
           __nv_bfloat16* __restrict__ ehi, __nv_bfloat16* __restrict__ elo,
           const float* __restrict__ asrc, const float* __restrict__ adst, int dots) {
    extern __shared__ char sm[];
    uint32_t sb = smem_u32(sm);
    const int tid = threadIdx.x, lane = tid & 31, wid = tid >> 5;
    const int warp_m = wid & 1;        // 2 m-warps of 32 rows
    const int warp_n = wid >> 1;       // 4 n-warps of 32 cols
    const int colBase = blockIdx.x * 128;
    const int rowBase = blockIdx.y * MTILE;

    float acc[2][4][4] = {};

    load_stage(sb, 0, 0, rowBase, colBase, tid, ahi, alo, bhi, blo);
    asm volatile("cp.async.commit_group;" ::: "memory");

    for (int s = 0; s < 8; s++) {
        if (s + 1 < 8) load_stage(sb, (s + 1) & 1, s + 1, rowBase, colBase, tid, ahi, alo, bhi, blo);
        asm volatile("cp.async.commit_group;" ::: "memory");
        asm volatile("cp.async.wait_group 1;" ::: "memory");
        __syncthreads();

        uint32_t stg = sb + (s & 1) * STAGE_BYTES;
        #pragma unroll
        for (int k16 = 0; k16 < 2; k16++) {
            int chunk = k16 * 2 + (lane >> 4);
            uint32_t ah[2][4], al[2][4];
            #pragma unroll
            for (int mf = 0; mf < 2; mf++) {
                int arow = warp_m * 32 + mf * 16 + (lane & 15);
                ldsm4(ah[mf], stg + 0    + swz(arow, chunk));
                ldsm4(al[mf], stg + 4096 + swz(arow, chunk));
            }
            #pragma unroll
            for (int nb = 0; nb < 2; nb++) {
                uint32_t bhr[4], blr[4];
                int brow = warp_n * 32 + nb * 16 + (lane & 15);
                ldsm4(bhr, stg + 8192  + swz(brow, chunk));
                ldsm4(blr, stg + 16384 + swz(brow, chunk));
                #pragma unroll
                for (int mf = 0; mf < 2; mf++)
                    #pragma unroll
                    for (int h = 0; h < 2; h++) {
                        float* d = acc[mf][nb * 2 + h];
                        mma_bf16(d, ah[mf], bhr[h], bhr[h + 2]);
                        mma_bf16(d, ah[mf], blr[h], blr[h + 2]);
                        mma_bf16(d, al[mf], bhr[h], bhr[h + 2]);
                    }
            }
        }
        __syncthreads();
    }

    // ---- epilogue: store C (+ optional split emit, + attention-dot atomics) ----
    #pragma unroll
    for (int mf = 0; mf < 2; mf++) {
        int r0 = rowBase + warp_m * 32 + mf * 16 + (lane >> 2);
        float s0 = 0.f, s1 = 0.f, d0 = 0.f, d1 = 0.f;
        #pragma unroll
        for (int nf = 0; nf < 4; nf++) {
            int col = colBase + warp_n * 32 + nf * 8 + (lane & 3) * 2;
            #pragma unroll
            for (int half = 0; half < 2; half++) {
                int r = r0 + half * 8;
                if (r < NN) {
                    float v0 = acc[mf][nf][2 * half], v1 = acc[mf][nf][2 * half + 1];
                    *(float2*)(out + (size_t)r * DD + col) = make_float2(v0, v1);
                    if (ehi) {
                        __nv_bfloat16 h0 = __float2bfloat16(v0);
                        __nv_bfloat16 h1 = __float2bfloat16(v1);
                        *(__nv_bfloat162*)(ehi + (size_t)r * DD + col) = __halves2bfloat162(h0, h1);
                        *(__nv_bfloat162*)(elo + (size_t)r * DD + col) = __halves2bfloat162(
                            __float2bfloat16(v0 - __bfloat162float(h0)),
                            __float2bfloat16(v1 - __bfloat162float(h1)));
                    }
                }
            }
            if (dots) {
                float as0 = asrc[col], as1 = asrc[col + 1];
                float ad0 = adst[col], ad1 = adst[col + 1];
                s0 = fmaf(acc[mf][nf][0], as0, fmaf(acc[mf][nf][1], as1, s0));
                d0 = fmaf(acc[mf][nf][0], ad0, fmaf(acc[mf][nf][1], ad1, d0));
                s1 = fmaf(acc[mf][nf][2], as0, fmaf(acc[mf][nf][3], as1, s1));
                d1 = fmaf(acc[mf][nf][2], ad0, fmaf(acc[mf][nf][3], ad1, d1));
            }
        }
        if (dots) {
            #pragma unroll
            for (int o = 1; o <= 2; o <<= 1) {
                s0 += __shfl_xor_sync(0xFFFFFFFFu, s0, o);
                s1 += __shfl_xor_sync(0xFFFFFFFFu, s1, o);
                d0 += __shfl_xor_sync(0xFFFFFFFFu, d0, o);
                d1 += __shfl_xor_sync(0xFFFFFFFFu, d1, o);
            }
            if ((lane & 3) == 0) {
                if (r0 < NN)     { atomicAdd(&g_dt[r0], s0);     atomicAdd(&g_dt[NN + r0], d0); }
                if (r0 + 8 < NN) { atomicAdd(&g_dt[r0 + 8], s1); atomicAdd(&g_dt[NN + r0 + 8], d1); }
            }
        }
    }
}

// ---------------- fused GAT aggregate ----------------
#define MAXE 64
__global__ void __launch_bounds__(256)
k_gat(const float* __restrict__ bias, int dorelu) {
    __shared__ float sv[8][MAXE];
    __shared__ int   ss[8][MAXE];
    int wid = threadIdx.x >> 5, lane = threadIdx.x & 31;
    int n = blockIdx.x * 8 + wid;
    if (n >= NN) return;
    int start = g_rowptr[n], end = g_rowptr[n + 1];
    int deg = end - start;
    float ed = g_dt[NN + n];

    float acc[8] = {};
    float acc2[8] = {};
    float sum = 0.f;
    float m = -3.4e38f;

    if (deg <= MAXE) {
        for (int j0 = 0; j0 < deg; j0 += 32) {
            int j = j0 + lane;
            float v = -3.4e38f;
            if (j < deg) {
                int s = g_csrc[start + j];
                v = g_dt[s] + ed;
                v = v > 0.f ? v : 0.2f * v;
                sv[wid][j] = v;
                ss[wid][j] = s;
            }
            m = fmaxf(m, v);
        }
        #pragma unroll
        for (int o = 16; o > 0; o >>= 1) m = fmaxf(m, __shfl_xor_sync(0xFFFFFFFFu, m, o));
        __syncwarp();
        // 2-edge unrolled gather: independent load/acc banks for MLP
        int j = 0;
        for (; j + 1 < deg; j += 2) {
            float ee0 = __expf(sv[wid][j] - m);
            float ee1 = __expf(sv[wid][j + 1] - m);
            sum += ee0 + ee1;
            const float4* row0 = (const float4*)(g_hw + (size_t)ss[wid][j] * DD);
            const float4* row1 = (const float4*)(g_hw + (size_t)ss[wid][j + 1] * DD);
            float4 a0 = row0[lane], b0 = row0[lane + 32];
            float4 a1 = row1[lane], b1 = row1[lane + 32];
            acc[0] = fmaf(ee0, a0.x, acc[0]);  acc[1] = fmaf(ee0, a0.y, acc[1]);
            acc[2] = fmaf(ee0, a0.z, acc[2]);  acc[3] = fmaf(ee0, a0.w, acc[3]);
            acc[4] = fmaf(ee0, b0.x, acc[4]);  acc[5] = fmaf(ee0, b0.y, acc[5]);
            acc[6] = fmaf(ee0, b0.z, acc[6]);  acc[7] = fmaf(ee0, b0.w, acc[7]);
            acc2[0] = fmaf(ee1, a1.x, acc2[0]); acc2[1] = fmaf(ee1, a1.y, acc2[1]);
            acc2[2] = fmaf(ee1, a1.z, acc2[2]); acc2[3] = fmaf(ee1, a1.w, acc2[3]);
            acc2[4] = fmaf(ee1, b1.x, acc2[4]); acc2[5] = fmaf(ee1, b1.y, acc2[5]);
            acc2[6] = fmaf(ee1, b1.z, acc2[6]); acc2[7] = fmaf(ee1, b1.w, acc2[7]);
        }
        if (j < deg) {
            float ee = __expf(sv[wid][j] - m);
            sum += ee;
            const float4* row = (const float4*)(g_hw + (size_t)ss[wid][j] * DD);
            float4 a = row[lane], b = row[lane + 32];
            acc[0] = fmaf(ee, a.x, acc[0]); acc[1] = fmaf(ee, a.y, acc[1]);
            acc[2] = fmaf(ee, a.z, acc[2]); acc[3] = fmaf(ee, a.w, acc[3]);
            acc[4] = fmaf(ee, b.x, acc[4]); acc[5] = fmaf(ee, b.y, acc[5]);
            acc[6] = fmaf(ee, b.z, acc[6]); acc[7] = fmaf(ee, b.w, acc[7]);
        }
        #pragma unroll
        for (int q = 0; q < 8; q++) acc[q] += acc2[q];
    } else {
        for (int j = start + lane; j < end; j += 32) {
            float v = g_dt[g_csrc[j]] + ed;
            v = v > 0.f ? v : 0.2f * v;
            m = fmaxf(m, v);
        }
        #pragma unroll
        for (int o = 16; o > 0; o >>= 1) m = fmaxf(m, __shfl_xor_sync(0xFFFFFFFFu, m, o));
        for (int j = start; j < end; j++) {
            int s = g_csrc[j];
            float v = g_dt[s] + ed;
            v = v > 0.f ? v : 0.2f * v;
            float ee = __expf(v - m);
            sum += ee;
            const float4* row = (const float4*)(g_hw + (size_t)s * DD);
            float4 a = row[lane], b = row[lane + 32];
            acc[0] = fmaf(ee, a.x, acc[0]); acc[1] = fmaf(ee, a.y, acc[1]);
            acc[2] = fmaf(ee, a.z, acc[2]); acc[3] = fmaf(ee, a.w, acc[3]);
            acc[4] = fmaf(ee, b.x, acc[4]); acc[5] = fmaf(ee, b.y, acc[5]);
            acc[6] = fmaf(ee, b.z, acc[6]); acc[7] = fmaf(ee, b.w, acc[7]);
        }
    }
    float inv = (deg > 0) ? 1.0f / sum : 0.f;

    float4 b0 = ((const float4*)bias)[lane];
    float4 b1 = ((const float4*)bias)[lane + 32];
    float o[8] = {acc[0] * inv + b0.x, acc[1] * inv + b0.y,
                  acc[2] * inv + b0.z, acc[3] * inv + b0.w,
                  acc[4] * inv + b1.x, acc[5] * inv + b1.y,
                  acc[6] * inv + b1.z, acc[7] * inv + b1.w};
    if (dorelu) {
        #pragma unroll
        for (int j = 0; j < 8; j++) o[j] = fmaxf(o[j], 0.f);
    }
    __nv_bfloat162 hp[4], lp[4];
    #pragma unroll
    for (int j = 0; j < 4; j++) {
        __nv_bfloat16 h0 = __float2bfloat16(o[2 * j]);
        __nv_bfloat16 h1 = __float2bfloat16(o[2 * j + 1]);
        hp[j] = __halves2bfloat162(h0, h1);
        lp[j] = __halves2bfloat162(__float2bfloat16(o[2 * j] - __bfloat162float(h0)),
                                   __float2bfloat16(o[2 * j + 1] - __bfloat162float(h1)));
    }
    __nv_bfloat16* dh = g_ahi + (size_t)n * DD;
    __nv_bfloat16* dl = g_alo + (size_t)n * DD;
    *(uint2*)(dh + 4 * lane)       = make_uint2(((uint2*)hp)[0].x, ((uint2*)hp)[0].y);
    *(uint2*)(dh + 128 + 4 * lane) = make_uint2(((uint2*)hp)[1].x, ((uint2*)hp)[1].y);
    *(uint2*)(dl + 4 * lane)       = make_uint2(((uint2*)lp)[0].x, ((uint2*)lp)[0].y);
    *(uint2*)(dl + 128 + 4 * lane) = make_uint2(((uint2*)lp)[1].x, ((uint2*)lp)[1].y);
}

// ---------------- launch ----------------
extern "C" void kernel_launch(void* const* d_in, const int* in_sizes, int n_in,
                              void* d_out, int out_size) {
    const float* x     = (const float*)d_in[0];
    const void*  ei    = d_in[1];
    const float* W1    = (const float*)d_in[2];
    const float* W2    = (const float*)d_in[3];
    const float* Ws    = (const float*)d_in[4];
    const float* a_src = (const float*)d_in[5];
    const float* a_dst = (const float*)d_in[6];
    const float* bias  = (const float*)d_in[7];
    const float* W3    = (const float*)d_in[8];
    float* out = (float*)d_out;

    float *p_hw, *p_dt;
    int* p_deg;
    __nv_bfloat16 *p_ahi, *p_alo, *p_a2hi, *p_a2lo, *p_bhi, *p_blo;
    cudaGetSymbolAddress((void**)&p_hw,   g_hw);
    cudaGetSymbolAddress((void**)&p_dt,   g_dt);
    cudaGetSymbolAddress((void**)&p_deg,  g_deg);
    cudaGetSymbolAddress((void**)&p_ahi,  g_ahi);
    cudaGetSymbolAddress((void**)&p_alo,  g_alo);
    cudaGetSymbolAddress((void**)&p_a2hi, g_a2hi);
    cudaGetSymbolAddress((void**)&p_a2lo, g_a2lo);
    cudaGetSymbolAddress((void**)&p_bhi,  g_bhi);
    cudaGetSymbolAddress((void**)&p_blo,  g_blo);

    cudaFuncSetAttribute(k_gemm_mma, cudaFuncAttributeMaxDynamicSharedMemorySize, SMEM_BYTES);

    // one-time: indices, CSR, x split, all weight splits
    k_detect<<<1, 128>>>((const int*)ei);
    cudaMemsetAsync(p_deg, 0, NN * sizeof(int));
    k_convert<<<(EE + 255) / 256, 256>>>(ei);
    k_scan<<<1, 1024>>>();
    k_fill<<<(EE + 255) / 256, 256>>>();
    k_convA<<<(NN * DD / 8 + 255) / 256, 256>>>(x);
    k_prepAllB<<<(9 * DD * DD + 255) / 256, 256>>>(W1, W2, Ws, W3);

    dim3 gg(2, (NN + MTILE - 1) / MTILE);   // (2, 313)
    const int BW = DD * DD;

    // hw = x@W1 (emit split to S1); h = hw@W2 (emit split to S0)
    k_gemm_mma<<<gg, GT, SMEM_BYTES>>>(p_hw, p_ahi, p_alo, p_bhi, p_blo,
                                       p_a2hi, p_a2lo, nullptr, nullptr, 0);
    k_gemm_mma<<<gg, GT, SMEM_BYTES>>>(p_hw, p_a2hi, p_a2lo, p_bhi + BW, p_blo + BW,
                                       p_ahi, p_alo, nullptr, nullptr, 0);

    for (int l = 0; l < 6; l++) {
        cudaMemsetAsync(p_dt, 0, 2 * NN * sizeof(float));
        k_gemm_mma<<<gg, GT, SMEM_BYTES>>>(p_hw, p_ahi, p_alo,
                                           p_bhi + (size_t)(2 + l) * BW, p_blo + (size_t)(2 + l) * BW,
                                           nullptr, nullptr, a_src + l * DD, a_dst + l * DD, 1);
        k_gat<<<(NN + 7) / 8, 256>>>(bias + l * DD, l == 5 ? 1 : 0);
    }

    // out = relu(h) @ (W3_top + W3_bot)   (relu folded into last k_gat's split)
    k_gemm_mma<<<gg, GT, SMEM_BYTES>>>(out, p_ahi, p_alo, p_bhi + 8 * BW, p_blo + 8 * BW,
                                       nullptr, nullptr, nullptr, nullptr, 0);
}